// round 7
// baseline (speedup 1.0000x reference)
#include <cuda_runtime.h>
#include <math.h>

#define NC 128   // clusters
#define ND 64    // dimension

// V_FACTOR = 2*pi^32/(64*31!) — reference multiplies det by this in fp32; the
// product underflows (FTZ -> 0) for tiny dets, which drives the validity mask.
#define V_FACTOR_D 3.080513e-20
#define FLT_MIN_NORMAL 1.1754943508222875e-38

// ---------------- device scratch (no allocations allowed) ----------------
static __device__ __align__(16) float g_mu[NC * ND];
static __device__ __align__(16) float g_Smod[ND * ND];   // the one mutated S row
static __device__ __align__(16) float g_ZZ[NC * ND * ND];
static __device__ float  g_n[NC];
static __device__ float  g_Gamma[NC];
static __device__ float  g_Vii32[NC];
static __device__ double g_Vii64[NC];
static __device__ float  g_kappa[NC * NC];
static __device__ int    g_active[NC];
static __device__ int    g_sel[NC];
static __device__ int    g_modidx;
static __device__ int    g_ncand;
static __device__ int    g_kmin_key;     // order-preserving int key of min kappa
static __device__ int    g_cand[128];
static __device__ double g_kval[128];

__device__ __forceinline__ float  f_inf() { return __int_as_float(0x7f800000); }
__device__ __forceinline__ double d_inf() { return __longlong_as_double(0x7ff0000000000000LL); }

__device__ __forceinline__ int f2key(float f) {
    int b = __float_as_int(f);
    return (b >= 0) ? b : (int)(~(unsigned)b);
}
__device__ __forceinline__ float key2f(int k) {
    return __int_as_float((k >= 0) ? k : (int)(~(unsigned)k));
}

// Emulate the reference's fp32 `V_ij = V_FACTOR*det > 0` test under FTZ.
__device__ __forceinline__ bool vij_valid(double det) {
    return (det > 0.0) && (det * V_FACTOR_D >= FLT_MIN_NORMAL);
}

// ---------------------------------------------------------------------------
// fp32 64x64 forward elimination, pivot-free (SPD inputs). 128 threads:
// row = tid>>1, half = tid&1 owns cols [32*half, +32). ONE barrier per step
// via double-buffered pivot rows (row k+1 publishes its fully-updated row
// into the alternate buffer during phase k). Pivots are stashed to s_pk[64];
// the determinant (and any pivot-based reduction) is computed AFTER the loop
// so no fp64 chain sits on the per-phase critical path.
// s_piv: 128 floats. s_pk: 64 floats. No return; caller reduces s_pk.
// ---------------------------------------------------------------------------
__device__ __forceinline__ void block_elim64f(float a[32], float* s_piv, float* s_pk) {
    const int tid  = threadIdx.x;
    const int row  = tid >> 1;
    const int half = tid & 1;
    const int c0   = half << 5;
    if (row == 0) {
#pragma unroll
        for (int q = 0; q < 8; ++q)
            reinterpret_cast<float4*>(s_piv)[half * 8 + q] =
                make_float4(a[4*q], a[4*q+1], a[4*q+2], a[4*q+3]);
    }
    __syncthreads();
#pragma unroll
    for (int k = 0; k < 64; ++k) {
        const float* buf = s_piv + ((k & 1) << 6);
        float pk = buf[k];
        if (tid == 0) s_pk[k] = pk;
        float cand  = a[k & 31];
        float other = __shfl_xor_sync(0xffffffffu, cand, 1);
        float fr    = ((k >> 5) == half) ? cand : other;
        float f     = __fdividef(fr, pk);
        if (row > k) {
#pragma unroll
            for (int q = 0; q < 8; ++q) {
                if (c0 + 4*q + 3 >= k) {
                    float4 p = reinterpret_cast<const float4*>(buf)[half * 8 + q];
                    a[4*q]   -= f * p.x;
                    a[4*q+1] -= f * p.y;
                    a[4*q+2] -= f * p.z;
                    a[4*q+3] -= f * p.w;
                }
            }
        }
        if (row == k + 1) {
            float* nb = s_piv + (((k + 1) & 1) << 6);
#pragma unroll
            for (int q = 0; q < 8; ++q)
                reinterpret_cast<float4*>(nb)[half * 8 + q] =
                    make_float4(a[4*q], a[4*q+1], a[4*q+2], a[4*q+3]);
        }
        __syncthreads();
    }
}

// Warp-0 product of the 64 stashed pivots (call with all threads; result on
// thread 0, garbage elsewhere).
__device__ __forceinline__ double pivot_product(const float* s_pk) {
    const int tid = threadIdx.x;
    double v = 1.0;
    if (tid < 32) {
        v = (double)s_pk[tid] * (double)s_pk[tid + 32];
#pragma unroll
        for (int off = 16; off; off >>= 1)
            v *= __shfl_down_sync(0xffffffffu, v, off);
    }
    return v;
}

// ---------------------------------------------------------------------------
// fp64 single-step engine — only candidate refinement (few blocks). One fp64
// division per step (broadcast 1/pk), double2 pivot loads, 1 barrier/step.
// ---------------------------------------------------------------------------
__device__ __forceinline__ double block_det64d(double a[32], double* s_piv, double* s_inv) {
    const int tid  = threadIdx.x;
    const int row  = tid >> 1;
    const int half = tid & 1;
    const int c0   = half << 5;
    if (row == 0) {
#pragma unroll
        for (int q = 0; q < 16; ++q)
            reinterpret_cast<double2*>(s_piv)[half * 16 + q] = make_double2(a[2*q], a[2*q+1]);
        if (tid == 0) s_inv[0] = 1.0 / a[0];
    }
    __syncthreads();
    double det = 1.0;
#pragma unroll
    for (int k = 0; k < 64; ++k) {
        const double* buf = s_piv + ((k & 1) << 6);
        double pk  = buf[k];
        double ipk = s_inv[k & 1];
        if (tid == 0) det *= pk;
        double cand  = a[k & 31];
        double other = __shfl_xor_sync(0xffffffffu, cand, 1);
        double fr    = ((k >> 5) == half) ? cand : other;
        double f     = fr * ipk;
        if (row > k) {
#pragma unroll
            for (int q = 0; q < 16; ++q) {
                if (c0 + 2*q + 1 >= k) {
                    double2 p = reinterpret_cast<const double2*>(buf)[half * 16 + q];
                    a[2*q]   -= f * p.x;
                    a[2*q+1] -= f * p.y;
                }
            }
        }
        if (row == k + 1) {
            double* nb = s_piv + (((k + 1) & 1) << 6);
#pragma unroll
            for (int q = 0; q < 16; ++q)
                reinterpret_cast<double2*>(nb)[half * 16 + q] = make_double2(a[2*q], a[2*q+1]);
            if (((k + 1) >> 5) == half) s_inv[(k + 1) & 1] = 1.0 / a[(k + 1) & 31];
        }
        __syncthreads();
    }
    return det;
}

// ---------------------------------------------------------------------------
// K1 (merged k0+k1+k3): per cluster c —
//  - copy mu row / n / active into working state (block 0 resets reductions)
//  - ZZ_c = ((n-1)/n) S + mu mu^T            (input-based; k3_fix patches the
//  - Vii32_c = det(S/n) (pivot product)       one cluster k2 mutates)
//  - d2 (euclidean, or LDL^T quadratic form e'A^{-1}e = sum x_k^2/p_k when
//    n >= 100, from the SAME elimination), Gamma = active ? exp(-d2) : 0
// ---------------------------------------------------------------------------
__global__ void __launch_bounds__(128, 6)
k1_gamma(const float* __restrict__ z, const float* __restrict__ mu_in,
         const float* __restrict__ S_in, const float* __restrict__ n_in,
         const int* __restrict__ cact) {
    const int c = blockIdx.x;
    const int tid = threadIdx.x;
    __shared__ float s_piv[128];
    __shared__ float s_pk[64];
    __shared__ float s_x[64];
    __shared__ float s_e[64];
    const float nc = n_in[c];
    if (tid < 64) {
        float m = mu_in[c * ND + tid];
        g_mu[c * ND + tid] = m;
        float e = z[tid] - m;
        s_e[tid] = e;
        s_x[tid] = e;
    }
    if (tid == 0) {
        g_n[c] = nc;
        g_active[c] = (c < cact[0]) ? 1 : 0;
        if (c == 0) { g_kmin_key = 0x7f800000; g_ncand = 0; }
    }
    // ZZ build from INPUT S, mu (valid for every cluster k2 does not touch)
    {
        const float coef = (nc - 1.0f) / nc;
        const float* mc = mu_in + c * ND;
        const float4* Sc4 = reinterpret_cast<const float4*>(S_in + c * ND * ND);
        const float4* mc4 = reinterpret_cast<const float4*>(mc);
        float4* Z4 = reinterpret_cast<float4*>(&g_ZZ[c * ND * ND]);
        for (int t = tid; t < ND * ND / 4; t += 128) {
            float4 s = Sc4[t];
            float4 m = mc4[t & 15];
            float mr = mc[t >> 4];
            Z4[t] = make_float4(coef * s.x + mr * m.x, coef * s.y + mr * m.y,
                                coef * s.z + mr * m.z, coef * s.w + mr * m.w);
        }
    }
    // elimination on S/n with RHS solve
    const float invn = 1.0f / nc;
    const int row  = tid >> 1;
    const int half = tid & 1;
    const int c0   = half << 5;
    float a[32];
    {
        const float4* Sr = reinterpret_cast<const float4*>(S_in + c * ND * ND + row * ND + c0);
#pragma unroll
        for (int q = 0; q < 8; ++q) {
            float4 v = Sr[q];
            a[4*q]   = v.x * invn;
            a[4*q+1] = v.y * invn;
            a[4*q+2] = v.z * invn;
            a[4*q+3] = v.w * invn;
        }
    }
    if (row == 0) {
#pragma unroll
        for (int q = 0; q < 8; ++q)
            reinterpret_cast<float4*>(s_piv)[half * 8 + q] =
                make_float4(a[4*q], a[4*q+1], a[4*q+2], a[4*q+3]);
    }
    __syncthreads();
#pragma unroll
    for (int k = 0; k < 64; ++k) {
        const float* buf = s_piv + ((k & 1) << 6);
        float pk = buf[k];
        float xk = s_x[k];
        if (tid == 0) s_pk[k] = pk;
        float cand  = a[k & 31];
        float other = __shfl_xor_sync(0xffffffffu, cand, 1);
        float fr    = ((k >> 5) == half) ? cand : other;
        float f     = __fdividef(fr, pk);
        if (row > k) {
#pragma unroll
            for (int q = 0; q < 8; ++q) {
                if (c0 + 4*q + 3 >= k) {
                    float4 p = reinterpret_cast<const float4*>(buf)[half * 8 + q];
                    a[4*q]   -= f * p.x;
                    a[4*q+1] -= f * p.y;
                    a[4*q+2] -= f * p.z;
                    a[4*q+3] -= f * p.w;
                }
            }
            if (half == 0) s_x[row] -= f * xk;   // one writer per row
        }
        if (row == k + 1) {
            float* nb = s_piv + (((k + 1) & 1) << 6);
#pragma unroll
            for (int q = 0; q < 8; ++q)
                reinterpret_cast<float4*>(nb)[half * 8 + q] =
                    make_float4(a[4*q], a[4*q+1], a[4*q+2], a[4*q+3]);
        }
        __syncthreads();
    }
    // post-loop reductions (warp 0): d2_euc, d2_mah, det
    if (tid < 32) {
        float e0 = s_e[tid], e1 = s_e[tid + 32];
        float x0 = s_x[tid], x1 = s_x[tid + 32];
        float p0 = s_pk[tid], p1 = s_pk[tid + 32];
        float deuc = e0 * e0 + e1 * e1;
        double dmah = (double)(x0 * x0) / (double)p0 + (double)(x1 * x1) / (double)p1;
        double dprod = (double)p0 * (double)p1;
#pragma unroll
        for (int off = 16; off; off >>= 1) {
            deuc  += __shfl_down_sync(0xffffffffu, deuc, off);
            dmah  += __shfl_down_sync(0xffffffffu, dmah, off);
            dprod *= __shfl_down_sync(0xffffffffu, dprod, off);
        }
        if (tid == 0) {
            float d2 = (nc < 100.0f) ? deuc : (float)dmah;
            g_Gamma[c] = (c < cact[0]) ? expf(-d2) : 0.0f;
            g_Vii32[c] = (float)dprod;
        }
    }
}

// ---------------------------------------------------------------------------
// K2: warp-parallel argmax Gamma (first-index ties), incremental update or
// spawn (S mutation stored as g_Smod + g_modidx), then sel.
// ---------------------------------------------------------------------------
__global__ void k2_update(const float* __restrict__ z, const float* __restrict__ S_in,
                          const int* __restrict__ cact) {
    const int tid = threadIdx.x;   // 256
    __shared__ float s_ej[64];
    __shared__ int s_j, s_incr;
    __shared__ float s_nj;
    if (tid < 32) {
        float bv = g_Gamma[tid]; int bi = tid;
#pragma unroll
        for (int t = 1; t < 4; ++t) {
            float v = g_Gamma[tid + 32 * t];
            if (v > bv) { bv = v; bi = tid + 32 * t; }   // increasing idx: strict >
        }
#pragma unroll
        for (int off = 16; off; off >>= 1) {
            float ov = __shfl_down_sync(0xffffffffu, bv, off);
            int   oi = __shfl_down_sync(0xffffffffu, bi, off);
            if (ov > bv || (ov == bv && oi < bi)) { bv = ov; bi = oi; }
        }
        if (tid == 0) {
            s_j = bi;
            s_incr = (bv > 0.9f) ? 1 : 0;
            s_nj = g_n[bi];
        }
    }
    __syncthreads();
    if (s_incr) {
        const int j = s_j;
        if (tid < 64) s_ej[tid] = z[tid] - g_mu[j * ND + tid];
        __syncthreads();
        if (tid < 64) g_mu[j * ND + tid] += s_ej[tid] / (1.0f + s_nj);
        for (int idx = tid; idx < ND * ND; idx += 256)
            g_Smod[idx] = S_in[j * ND * ND + idx] + s_ej[idx >> 6] * s_ej[idx & 63];
        if (tid == 0) { g_n[j] = s_nj + 1.0f; g_modidx = j; }
    } else {
        const int ca = cact[0];
        if (tid < 64) g_mu[ca * ND + tid] = z[tid];
        for (int idx = tid; idx < ND * ND; idx += 256)
            g_Smod[idx] = ((idx >> 6) == (idx & 63)) ? 1.0f : 0.0f;
        if (tid == 0) { g_n[ca] = 1.0f; g_Gamma[ca] = 1.0f; g_active[ca] = 1; g_modidx = ca; }
    }
    __syncthreads();
    if (tid < NC)
        g_sel[tid] = (g_Gamma[tid] > 0.225f && g_active[tid]) ? 1 : 0;
}

__device__ __forceinline__ const float* S_eff(const float* S_in, int c) {
    return (c == g_modidx) ? g_Smod : (S_in + c * ND * ND);
}

// ---------------------------------------------------------------------------
// K3fix (1 block): rebuild ZZ and Vii32 for the single cluster k2 mutated,
// using the POST-update S (g_Smod), mu, n.
// ---------------------------------------------------------------------------
__global__ void __launch_bounds__(128, 6)
k3_fix() {
    const int c = g_modidx;
    const int tid = threadIdx.x;
    __shared__ float s_piv[128];
    __shared__ float s_pk[64];
    const float nc   = g_n[c];
    const float coef = (nc - 1.0f) / nc;
    const float invn = 1.0f / nc;
    const float* mc = &g_mu[c * ND];
    const float4* Sc4 = reinterpret_cast<const float4*>(g_Smod);
    const float4* mc4 = reinterpret_cast<const float4*>(mc);
    float4* Z4 = reinterpret_cast<float4*>(&g_ZZ[c * ND * ND]);
    for (int t = tid; t < ND * ND / 4; t += 128) {
        float4 s = Sc4[t];
        float4 m = mc4[t & 15];
        float mr = mc[t >> 4];
        Z4[t] = make_float4(coef * s.x + mr * m.x, coef * s.y + mr * m.y,
                            coef * s.z + mr * m.z, coef * s.w + mr * m.w);
    }
    const int row = tid >> 1;
    const int c0  = (tid & 1) << 5;
    float a[32];
    const float4* Sr = reinterpret_cast<const float4*>(g_Smod + row * ND + c0);
#pragma unroll
    for (int q = 0; q < 8; ++q) {
        float4 v = Sr[q];
        a[4*q]   = v.x * invn;
        a[4*q+1] = v.y * invn;
        a[4*q+2] = v.z * invn;
        a[4*q+3] = v.w * invn;
    }
    block_elim64f(a, s_piv, s_pk);
    double det = pivot_product(s_pk);
    if (tid == 0) g_Vii32[c] = (float)det;
}

// ---------------------------------------------------------------------------
// K4 (SCREEN): one block per (i,j). Sigma in fp32 registers, elimination,
// kappa32 with the FTZ validity mask; feeds global kmin via atomicMin.
// ---------------------------------------------------------------------------
__global__ void __launch_bounds__(128, 6)
k4_pairs() {
    const int b = blockIdx.x;
    const int i = b >> 7;
    const int j = b & (NC - 1);
    const int tid = threadIdx.x;
    if (i >= j || !g_sel[i] || !g_sel[j]) {
        if (tid == 0) g_kappa[b] = f_inf();
        return;
    }
    __shared__ float s_piv[128];
    __shared__ float s_pk[64];
    __shared__ float s_muij[64];
    const float ni = g_n[i], nj = g_n[j];
    const float nij = ni + nj;
    if (tid < 64)
        s_muij[tid] = (ni * g_mu[i * ND + tid] + nj * g_mu[j * ND + tid]) / nij;
    __syncthreads();
    const float invs = 1.0f / (nij - 1.0f);
    const int row = tid >> 1;
    const int c0  = (tid & 1) << 5;
    const float mr = s_muij[row];
    const float4* zi = reinterpret_cast<const float4*>(&g_ZZ[i * ND * ND + row * ND + c0]);
    const float4* zj = reinterpret_cast<const float4*>(&g_ZZ[j * ND * ND + row * ND + c0]);
    float a[32];
#pragma unroll
    for (int q = 0; q < 8; ++q) {
        float4 x = zi[q];
        float4 y = zj[q];
        a[4*q]   = (x.x + y.x - mr * s_muij[c0 + 4*q])     * invs;
        a[4*q+1] = (x.y + y.y - mr * s_muij[c0 + 4*q + 1]) * invs;
        a[4*q+2] = (x.z + y.z - mr * s_muij[c0 + 4*q + 2]) * invs;
        a[4*q+3] = (x.w + y.w - mr * s_muij[c0 + 4*q + 3]) * invs;
    }
    block_elim64f(a, s_piv, s_pk);
    double det = pivot_product(s_pk);
    if (tid == 0) {
        float kap = vij_valid(det) ? ((float)(det / (double)(g_Vii32[i] + g_Vii32[j])))
                                   : f_inf();
        g_kappa[b] = kap;
        if (kap < f_inf()) atomicMin(&g_kmin_key, f2key(kap));
    }
}

// ---------------------------------------------------------------------------
// K5a: parallel candidate collection near the global fp32 kmin.
// ---------------------------------------------------------------------------
__global__ void k5a_select() {
    const float kmin = key2f(g_kmin_key);
    if (!(kmin < 3.0e38f)) return;
    const float thr = kmin + (fabsf(kmin) * 1e-3f + 1e-30f);
    const int b = blockIdx.x * 256 + threadIdx.x;
    if (g_kappa[b] <= thr) {
        int p = atomicAdd(&g_ncand, 1);
        if (p < 128) g_cand[p] = b;
    }
}

// ---------------------------------------------------------------------------
// K5b0: fp64 Vii for clusters referenced by candidates (lazy; few blocks).
// ---------------------------------------------------------------------------
__global__ void k5b0_vii(const float* __restrict__ S_in) {
    const int ncand = min(g_ncand, 128);
    const int t = blockIdx.x;
    if (t >= 2 * ncand) return;
    const int flat = g_cand[t >> 1];
    const int c = (t & 1) ? (flat & (NC - 1)) : (flat >> 7);
    const int tid = threadIdx.x;
    __shared__ double s_piv[128];
    __shared__ double s_inv[2];
    const double invn = 1.0 / (double)g_n[c];
    const float* Sc = S_eff(S_in, c);
    const int row = tid >> 1;
    const int c0  = (tid & 1) << 5;
    double a[32];
    const float* Sr = Sc + row * ND + c0;
#pragma unroll
    for (int q = 0; q < 32; ++q) a[q] = (double)Sr[q] * invn;
    double det = block_det64d(a, s_piv, s_inv);
    if (tid == 0) g_Vii64[c] = det;
}

// ---------------------------------------------------------------------------
// K5b: fp64 recompute of kappa for each candidate pair (same validity mask).
// ---------------------------------------------------------------------------
__global__ void k5b_refine() {
    const int b = blockIdx.x;
    const int ncand = min(g_ncand, 128);
    if (b >= ncand) return;
    const int tid = threadIdx.x;
    __shared__ double s_piv[128];
    __shared__ double s_inv[2];
    __shared__ double s_muij[64];
    const int flat = g_cand[b];
    const int i = flat >> 7;
    const int j = flat & (NC - 1);
    const double ni = (double)g_n[i], nj = (double)g_n[j];
    const double nij = ni + nj;
    if (tid < 64)
        s_muij[tid] = (ni * (double)g_mu[i * ND + tid] + nj * (double)g_mu[j * ND + tid]) / nij;
    __syncthreads();
    const double invs = 1.0 / (nij - 1.0);
    const int row = tid >> 1;
    const int c0  = (tid & 1) << 5;
    const double mr = s_muij[row];
    const float* zi = &g_ZZ[i * ND * ND + row * ND + c0];
    const float* zj = &g_ZZ[j * ND * ND + row * ND + c0];
    double a[32];
#pragma unroll
    for (int q = 0; q < 32; ++q)
        a[q] = ((double)zi[q] + (double)zj[q] - mr * s_muij[c0 + q]) * invs;
    double det = block_det64d(a, s_piv, s_inv);
    if (tid == 0)
        g_kval[b] = vij_valid(det) ? (det / (g_Vii64[i] + g_Vii64[j])) : d_inf();
}

// ---------------------------------------------------------------------------
// K5c: argmin over refined candidates (first-flat-index ties), conditional
// merge, write out = mu * active.
// ---------------------------------------------------------------------------
__global__ void k5c_final(float* __restrict__ out) {
    const int tid = threadIdx.x;   // 256
    __shared__ double s_val[256];
    __shared__ int    s_idx[256];
    const int ncand = min(g_ncand, 128);
    double bv = d_inf(); int bi = 0x7fffffff;
    for (int b = tid; b < ncand; b += 256) {
        double v = g_kval[b]; int fi = g_cand[b];
        if (v < bv || (v == bv && fi < bi)) { bv = v; bi = fi; }
    }
    s_val[tid] = bv; s_idx[tid] = bi;
    __syncthreads();
    for (int s = 128; s; s >>= 1) {
        if (tid < s) {
            double v2 = s_val[tid + s]; int i2 = s_idx[tid + s];
            if (v2 < s_val[tid] || (v2 == s_val[tid] && i2 < s_idx[tid])) {
                s_val[tid] = v2; s_idx[tid] = i2;
            }
        }
        __syncthreads();
    }
    __shared__ int s_mi, s_mj, s_do;
    __shared__ float s_nmi, s_nmj;
    if (tid == 0) {
        s_do = (s_val[0] < 0.9) ? 1 : 0;
        s_mi = s_idx[0] >> 7;
        s_mj = s_idx[0] & (NC - 1);
        if (s_do) { s_nmi = g_n[s_mi]; s_nmj = g_n[s_mj]; }
    }
    __syncthreads();
    if (s_do) {
        if (tid < 64) {
            const int mi = s_mi, mj = s_mj;
            g_mu[mi * ND + tid] =
                (s_nmi * g_mu[mi * ND + tid] + s_nmj * g_mu[mj * ND + tid]) / (s_nmi + s_nmj);
        }
        if (tid == 0) g_active[s_mj] = 0;
    }
    __syncthreads();
    for (int idx = tid; idx < NC * ND; idx += 256)
        out[idx] = g_active[idx >> 6] ? g_mu[idx] : 0.0f;
}

// ---------------------------------------------------------------------------
extern "C" void kernel_launch(void* const* d_in, const int* in_sizes, int n_in,
                              void* d_out, int out_size) {
    const float* z  = (const float*)d_in[0];
    const float* mu = (const float*)d_in[1];
    const float* S  = (const float*)d_in[2];
    const float* n  = (const float*)d_in[3];
    const int*   ca = (const int*)d_in[4];
    float* out = (float*)d_out;

    k1_gamma<<<NC, 128>>>(z, mu, S, n, ca);
    k2_update<<<1, 256>>>(z, S, ca);
    k3_fix<<<1, 128>>>();
    k4_pairs<<<NC * NC, 128>>>();
    k5a_select<<<64, 256>>>();
    k5b0_vii<<<256, 128>>>(S);
    k5b_refine<<<128, 128>>>();
    k5c_final<<<1, 256>>>(out);
}

// round 8
// speedup vs baseline: 1.1448x; 1.1448x over previous
#include <cuda_runtime.h>
#include <math.h>

#define NC 128   // clusters
#define ND 64    // dimension

// V_FACTOR = 2*pi^32/(64*31!) — reference multiplies det by this in fp32; the
// product underflows (FTZ -> 0) for tiny dets, which drives the validity mask.
#define V_FACTOR_D 3.080513e-20
#define FLT_MIN_NORMAL 1.1754943508222875e-38

// ---------------- device scratch (no allocations allowed) ----------------
static __device__ __align__(16) float g_mu[NC * ND];
static __device__ __align__(16) float g_Smod[ND * ND];   // the one mutated S row
static __device__ __align__(16) float g_ZZ[NC * ND * ND];
static __device__ float  g_n[NC];
static __device__ float  g_Gamma[NC];
static __device__ float  g_Vii32[NC];
static __device__ double g_Vii64[NC];
static __device__ float  g_kappa[NC * NC];
static __device__ int    g_active[NC];
static __device__ int    g_sel[NC];
static __device__ int    g_modidx;
static __device__ int    g_ncand;
static __device__ int    g_kmin_key;     // order-preserving int key of min kappa
static __device__ int    g_cand[128];
static __device__ double g_kval[128];

__device__ __forceinline__ float  f_inf() { return __int_as_float(0x7f800000); }
__device__ __forceinline__ double d_inf() { return __longlong_as_double(0x7ff0000000000000LL); }

__device__ __forceinline__ int f2key(float f) {
    int b = __float_as_int(f);
    return (b >= 0) ? b : (int)(~(unsigned)b);
}
__device__ __forceinline__ float key2f(int k) {
    return __int_as_float((k >= 0) ? k : (int)(~(unsigned)k));
}

// Emulate the reference's fp32 `V_ij = V_FACTOR*det > 0` test under FTZ.
__device__ __forceinline__ bool vij_valid(double det) {
    return (det > 0.0) && (det * V_FACTOR_D >= FLT_MIN_NORMAL);
}

// ---------------------------------------------------------------------------
// fp32 64x64 forward elimination (128-thread variant) — used by k1 / k3_fix.
// row = tid>>1, half = tid&1 owns cols [32*half, +32). 1 barrier/step via
// double-buffered pivot rows. Pivots stashed to s_pk for post-loop reduction.
// ---------------------------------------------------------------------------
__device__ __forceinline__ void block_elim64f(float a[32], float* s_piv, float* s_pk) {
    const int tid  = threadIdx.x;
    const int row  = tid >> 1;
    const int half = tid & 1;
    const int c0   = half << 5;
    if (row == 0) {
#pragma unroll
        for (int q = 0; q < 8; ++q)
            reinterpret_cast<float4*>(s_piv)[half * 8 + q] =
                make_float4(a[4*q], a[4*q+1], a[4*q+2], a[4*q+3]);
    }
    __syncthreads();
#pragma unroll
    for (int k = 0; k < 64; ++k) {
        const float* buf = s_piv + ((k & 1) << 6);
        float pk = buf[k];
        if (tid == 0) s_pk[k] = pk;
        float cand  = a[k & 31];
        float other = __shfl_xor_sync(0xffffffffu, cand, 1);
        float fr    = ((k >> 5) == half) ? cand : other;
        float f     = __fdividef(fr, pk);
        if (row > k) {
#pragma unroll
            for (int q = 0; q < 8; ++q) {
                if (c0 + 4*q + 3 >= k) {
                    float4 p = reinterpret_cast<const float4*>(buf)[half * 8 + q];
                    a[4*q]   -= f * p.x;
                    a[4*q+1] -= f * p.y;
                    a[4*q+2] -= f * p.z;
                    a[4*q+3] -= f * p.w;
                }
            }
        }
        if (row == k + 1) {
            float* nb = s_piv + (((k + 1) & 1) << 6);
#pragma unroll
            for (int q = 0; q < 8; ++q)
                reinterpret_cast<float4*>(nb)[half * 8 + q] =
                    make_float4(a[4*q], a[4*q+1], a[4*q+2], a[4*q+3]);
        }
        __syncthreads();
    }
}

// Warp-0 product of the 64 stashed pivots (result on thread 0).
__device__ __forceinline__ double pivot_product(const float* s_pk) {
    const int tid = threadIdx.x;
    double v = 1.0;
    if (tid < 32) {
        v = (double)s_pk[tid] * (double)s_pk[tid + 32];
#pragma unroll
        for (int off = 16; off; off >>= 1)
            v *= __shfl_down_sync(0xffffffffu, v, off);
    }
    return v;
}

// ---------------------------------------------------------------------------
// fp64 single-step engine — only candidate refinement (few blocks).
// ---------------------------------------------------------------------------
__device__ __forceinline__ double block_det64d(double a[32], double* s_piv, double* s_inv) {
    const int tid  = threadIdx.x;
    const int row  = tid >> 1;
    const int half = tid & 1;
    const int c0   = half << 5;
    if (row == 0) {
#pragma unroll
        for (int q = 0; q < 16; ++q)
            reinterpret_cast<double2*>(s_piv)[half * 16 + q] = make_double2(a[2*q], a[2*q+1]);
        if (tid == 0) s_inv[0] = 1.0 / a[0];
    }
    __syncthreads();
    double det = 1.0;
#pragma unroll
    for (int k = 0; k < 64; ++k) {
        const double* buf = s_piv + ((k & 1) << 6);
        double pk  = buf[k];
        double ipk = s_inv[k & 1];
        if (tid == 0) det *= pk;
        double cand  = a[k & 31];
        double other = __shfl_xor_sync(0xffffffffu, cand, 1);
        double fr    = ((k >> 5) == half) ? cand : other;
        double f     = fr * ipk;
        if (row > k) {
#pragma unroll
            for (int q = 0; q < 16; ++q) {
                if (c0 + 2*q + 1 >= k) {
                    double2 p = reinterpret_cast<const double2*>(buf)[half * 16 + q];
                    a[2*q]   -= f * p.x;
                    a[2*q+1] -= f * p.y;
                }
            }
        }
        if (row == k + 1) {
            double* nb = s_piv + (((k + 1) & 1) << 6);
#pragma unroll
            for (int q = 0; q < 16; ++q)
                reinterpret_cast<double2*>(nb)[half * 16 + q] = make_double2(a[2*q], a[2*q+1]);
            if (((k + 1) >> 5) == half) s_inv[(k + 1) & 1] = 1.0 / a[(k + 1) & 31];
        }
        __syncthreads();
    }
    return det;
}

// ---------------------------------------------------------------------------
// K1 (merged k0+k1+k3): init state, ZZ build, Vii32, Gamma.
// ---------------------------------------------------------------------------
__global__ void __launch_bounds__(128, 6)
k1_gamma(const float* __restrict__ z, const float* __restrict__ mu_in,
         const float* __restrict__ S_in, const float* __restrict__ n_in,
         const int* __restrict__ cact) {
    const int c = blockIdx.x;
    const int tid = threadIdx.x;
    __shared__ float s_piv[128];
    __shared__ float s_pk[64];
    __shared__ float s_x[64];
    __shared__ float s_e[64];
    const float nc = n_in[c];
    if (tid < 64) {
        float m = mu_in[c * ND + tid];
        g_mu[c * ND + tid] = m;
        float e = z[tid] - m;
        s_e[tid] = e;
        s_x[tid] = e;
    }
    if (tid == 0) {
        g_n[c] = nc;
        g_active[c] = (c < cact[0]) ? 1 : 0;
        if (c == 0) { g_kmin_key = 0x7f800000; g_ncand = 0; }
    }
    // ZZ build from INPUT S, mu (k3_fix patches the one mutated cluster)
    {
        const float coef = (nc - 1.0f) / nc;
        const float* mc = mu_in + c * ND;
        const float4* Sc4 = reinterpret_cast<const float4*>(S_in + c * ND * ND);
        const float4* mc4 = reinterpret_cast<const float4*>(mc);
        float4* Z4 = reinterpret_cast<float4*>(&g_ZZ[c * ND * ND]);
        for (int t = tid; t < ND * ND / 4; t += 128) {
            float4 s = Sc4[t];
            float4 m = mc4[t & 15];
            float mr = mc[t >> 4];
            Z4[t] = make_float4(coef * s.x + mr * m.x, coef * s.y + mr * m.y,
                                coef * s.z + mr * m.z, coef * s.w + mr * m.w);
        }
    }
    // elimination on S/n with RHS solve
    const float invn = 1.0f / nc;
    const int row  = tid >> 1;
    const int half = tid & 1;
    const int c0   = half << 5;
    float a[32];
    {
        const float4* Sr = reinterpret_cast<const float4*>(S_in + c * ND * ND + row * ND + c0);
#pragma unroll
        for (int q = 0; q < 8; ++q) {
            float4 v = Sr[q];
            a[4*q]   = v.x * invn;
            a[4*q+1] = v.y * invn;
            a[4*q+2] = v.z * invn;
            a[4*q+3] = v.w * invn;
        }
    }
    if (row == 0) {
#pragma unroll
        for (int q = 0; q < 8; ++q)
            reinterpret_cast<float4*>(s_piv)[half * 8 + q] =
                make_float4(a[4*q], a[4*q+1], a[4*q+2], a[4*q+3]);
    }
    __syncthreads();
#pragma unroll
    for (int k = 0; k < 64; ++k) {
        const float* buf = s_piv + ((k & 1) << 6);
        float pk = buf[k];
        float xk = s_x[k];
        if (tid == 0) s_pk[k] = pk;
        float cand  = a[k & 31];
        float other = __shfl_xor_sync(0xffffffffu, cand, 1);
        float fr    = ((k >> 5) == half) ? cand : other;
        float f     = __fdividef(fr, pk);
        if (row > k) {
#pragma unroll
            for (int q = 0; q < 8; ++q) {
                if (c0 + 4*q + 3 >= k) {
                    float4 p = reinterpret_cast<const float4*>(buf)[half * 8 + q];
                    a[4*q]   -= f * p.x;
                    a[4*q+1] -= f * p.y;
                    a[4*q+2] -= f * p.z;
                    a[4*q+3] -= f * p.w;
                }
            }
            if (half == 0) s_x[row] -= f * xk;   // one writer per row
        }
        if (row == k + 1) {
            float* nb = s_piv + (((k + 1) & 1) << 6);
#pragma unroll
            for (int q = 0; q < 8; ++q)
                reinterpret_cast<float4*>(nb)[half * 8 + q] =
                    make_float4(a[4*q], a[4*q+1], a[4*q+2], a[4*q+3]);
        }
        __syncthreads();
    }
    // post-loop reductions (warp 0): d2_euc, d2_mah, det
    if (tid < 32) {
        float e0 = s_e[tid], e1 = s_e[tid + 32];
        float x0 = s_x[tid], x1 = s_x[tid + 32];
        float p0 = s_pk[tid], p1 = s_pk[tid + 32];
        float deuc = e0 * e0 + e1 * e1;
        double dmah = (double)(x0 * x0) / (double)p0 + (double)(x1 * x1) / (double)p1;
        double dprod = (double)p0 * (double)p1;
#pragma unroll
        for (int off = 16; off; off >>= 1) {
            deuc  += __shfl_down_sync(0xffffffffu, deuc, off);
            dmah  += __shfl_down_sync(0xffffffffu, dmah, off);
            dprod *= __shfl_down_sync(0xffffffffu, dprod, off);
        }
        if (tid == 0) {
            float d2 = (nc < 100.0f) ? deuc : (float)dmah;
            g_Gamma[c] = (c < cact[0]) ? expf(-d2) : 0.0f;
            g_Vii32[c] = (float)dprod;
        }
    }
}

// ---------------------------------------------------------------------------
// K2: warp-parallel argmax Gamma, incremental update or spawn, then sel.
// ---------------------------------------------------------------------------
__global__ void k2_update(const float* __restrict__ z, const float* __restrict__ S_in,
                          const int* __restrict__ cact) {
    const int tid = threadIdx.x;   // 256
    __shared__ float s_ej[64];
    __shared__ int s_j, s_incr;
    __shared__ float s_nj;
    if (tid < 32) {
        float bv = g_Gamma[tid]; int bi = tid;
#pragma unroll
        for (int t = 1; t < 4; ++t) {
            float v = g_Gamma[tid + 32 * t];
            if (v > bv) { bv = v; bi = tid + 32 * t; }   // increasing idx: strict >
        }
#pragma unroll
        for (int off = 16; off; off >>= 1) {
            float ov = __shfl_down_sync(0xffffffffu, bv, off);
            int   oi = __shfl_down_sync(0xffffffffu, bi, off);
            if (ov > bv || (ov == bv && oi < bi)) { bv = ov; bi = oi; }
        }
        if (tid == 0) {
            s_j = bi;
            s_incr = (bv > 0.9f) ? 1 : 0;
            s_nj = g_n[bi];
        }
    }
    __syncthreads();
    if (s_incr) {
        const int j = s_j;
        if (tid < 64) s_ej[tid] = z[tid] - g_mu[j * ND + tid];
        __syncthreads();
        if (tid < 64) g_mu[j * ND + tid] += s_ej[tid] / (1.0f + s_nj);
        for (int idx = tid; idx < ND * ND; idx += 256)
            g_Smod[idx] = S_in[j * ND * ND + idx] + s_ej[idx >> 6] * s_ej[idx & 63];
        if (tid == 0) { g_n[j] = s_nj + 1.0f; g_modidx = j; }
    } else {
        const int ca = cact[0];
        if (tid < 64) g_mu[ca * ND + tid] = z[tid];
        for (int idx = tid; idx < ND * ND; idx += 256)
            g_Smod[idx] = ((idx >> 6) == (idx & 63)) ? 1.0f : 0.0f;
        if (tid == 0) { g_n[ca] = 1.0f; g_Gamma[ca] = 1.0f; g_active[ca] = 1; g_modidx = ca; }
    }
    __syncthreads();
    if (tid < NC)
        g_sel[tid] = (g_Gamma[tid] > 0.225f && g_active[tid]) ? 1 : 0;
}

__device__ __forceinline__ const float* S_eff(const float* S_in, int c) {
    return (c == g_modidx) ? g_Smod : (S_in + c * ND * ND);
}

// ---------------------------------------------------------------------------
// K3fix (1 block): rebuild ZZ and Vii32 for the single mutated cluster.
// ---------------------------------------------------------------------------
__global__ void __launch_bounds__(128, 6)
k3_fix() {
    const int c = g_modidx;
    const int tid = threadIdx.x;
    __shared__ float s_piv[128];
    __shared__ float s_pk[64];
    const float nc   = g_n[c];
    const float coef = (nc - 1.0f) / nc;
    const float invn = 1.0f / nc;
    const float* mc = &g_mu[c * ND];
    const float4* Sc4 = reinterpret_cast<const float4*>(g_Smod);
    const float4* mc4 = reinterpret_cast<const float4*>(mc);
    float4* Z4 = reinterpret_cast<float4*>(&g_ZZ[c * ND * ND]);
    for (int t = tid; t < ND * ND / 4; t += 128) {
        float4 s = Sc4[t];
        float4 m = mc4[t & 15];
        float mr = mc[t >> 4];
        Z4[t] = make_float4(coef * s.x + mr * m.x, coef * s.y + mr * m.y,
                            coef * s.z + mr * m.z, coef * s.w + mr * m.w);
    }
    const int row = tid >> 1;
    const int c0  = (tid & 1) << 5;
    float a[32];
    const float4* Sr = reinterpret_cast<const float4*>(g_Smod + row * ND + c0);
#pragma unroll
    for (int q = 0; q < 8; ++q) {
        float4 v = Sr[q];
        a[4*q]   = v.x * invn;
        a[4*q+1] = v.y * invn;
        a[4*q+2] = v.z * invn;
        a[4*q+3] = v.w * invn;
    }
    block_elim64f(a, s_piv, s_pk);
    double det = pivot_product(s_pk);
    if (tid == 0) g_Vii32[c] = (float)det;
}

// ---------------------------------------------------------------------------
// K4 (SCREEN): 64 threads/block, each owns TWO rows (r2, r2+32) x 32 cols.
// Pivot chunk loaded ONCE per step, applied to both rows -> half the L1
// wavefront traffic of the 1-row engine. Same arithmetic per element.
// ---------------------------------------------------------------------------
__global__ void __launch_bounds__(64, 8)
k4_pairs() {
    const int b = blockIdx.x;
    const int i = b >> 7;
    const int j = b & (NC - 1);
    const int tid = threadIdx.x;   // 64
    if (i >= j || !g_sel[i] || !g_sel[j]) {
        if (tid == 0) g_kappa[b] = f_inf();
        return;
    }
    __shared__ float s_piv[128];
    __shared__ float s_pk[64];
    __shared__ float s_muij[64];
    const float ni = g_n[i], nj = g_n[j];
    const float nij = ni + nj;
    s_muij[tid] = (ni * g_mu[i * ND + tid] + nj * g_mu[j * ND + tid]) / nij;
    __syncthreads();
    const float invs = 1.0f / (nij - 1.0f);
    const int r2   = tid >> 1;        // 0..31
    const int half = tid & 1;
    const int c0   = half << 5;
    const int r0 = r2, r1 = r2 + 32;
    float a0[32], a1[32];
    {
        const float mr0 = s_muij[r0], mr1 = s_muij[r1];
        const float4* zi0 = reinterpret_cast<const float4*>(&g_ZZ[i * ND * ND + r0 * ND + c0]);
        const float4* zj0 = reinterpret_cast<const float4*>(&g_ZZ[j * ND * ND + r0 * ND + c0]);
        const float4* zi1 = reinterpret_cast<const float4*>(&g_ZZ[i * ND * ND + r1 * ND + c0]);
        const float4* zj1 = reinterpret_cast<const float4*>(&g_ZZ[j * ND * ND + r1 * ND + c0]);
#pragma unroll
        for (int q = 0; q < 8; ++q) {
            float4 x = zi0[q], y = zj0[q];
            a0[4*q]   = (x.x + y.x - mr0 * s_muij[c0 + 4*q])     * invs;
            a0[4*q+1] = (x.y + y.y - mr0 * s_muij[c0 + 4*q + 1]) * invs;
            a0[4*q+2] = (x.z + y.z - mr0 * s_muij[c0 + 4*q + 2]) * invs;
            a0[4*q+3] = (x.w + y.w - mr0 * s_muij[c0 + 4*q + 3]) * invs;
            x = zi1[q]; y = zj1[q];
            a1[4*q]   = (x.x + y.x - mr1 * s_muij[c0 + 4*q])     * invs;
            a1[4*q+1] = (x.y + y.y - mr1 * s_muij[c0 + 4*q + 1]) * invs;
            a1[4*q+2] = (x.z + y.z - mr1 * s_muij[c0 + 4*q + 2]) * invs;
            a1[4*q+3] = (x.w + y.w - mr1 * s_muij[c0 + 4*q + 3]) * invs;
        }
    }
    // publish row 0 (threads with r2 == 0)
    if (r2 == 0) {
#pragma unroll
        for (int q = 0; q < 8; ++q)
            reinterpret_cast<float4*>(s_piv)[half * 8 + q] =
                make_float4(a0[4*q], a0[4*q+1], a0[4*q+2], a0[4*q+3]);
    }
    __syncthreads();
#pragma unroll
    for (int k = 0; k < 64; ++k) {
        const float* buf = s_piv + ((k & 1) << 6);
        float pk = buf[k];
        if (tid == 0) s_pk[k] = pk;
        // multipliers A[r0,k], A[r1,k] — owner half shares via shfl with partner
        float cand0 = a0[k & 31];
        float cand1 = a1[k & 31];
        float oth0  = __shfl_xor_sync(0xffffffffu, cand0, 1);
        float oth1  = __shfl_xor_sync(0xffffffffu, cand1, 1);
        const bool own = ((k >> 5) == half);
        float f0 = __fdividef(own ? cand0 : oth0, pk);
        float f1 = __fdividef(own ? cand1 : oth1, pk);
        const bool u0 = (r0 > k);
        const bool u1 = (r1 > k);
        if (u0 || u1) {
#pragma unroll
            for (int q = 0; q < 8; ++q) {
                if (c0 + 4*q + 3 >= k) {
                    float4 p = reinterpret_cast<const float4*>(buf)[half * 8 + q];
                    if (u0) {
                        a0[4*q]   -= f0 * p.x;
                        a0[4*q+1] -= f0 * p.y;
                        a0[4*q+2] -= f0 * p.z;
                        a0[4*q+3] -= f0 * p.w;
                    }
                    if (u1) {
                        a1[4*q]   -= f1 * p.x;
                        a1[4*q+1] -= f1 * p.y;
                        a1[4*q+2] -= f1 * p.z;
                        a1[4*q+3] -= f1 * p.w;
                    }
                }
            }
        }
        // publish row k+1 into the alternate buffer (a0 if k+1<32 else a1)
        if (k < 63 && r2 == ((k + 1) & 31)) {
            float* nb = s_piv + (((k + 1) & 1) << 6);
            if (k + 1 < 32) {
#pragma unroll
                for (int q = 0; q < 8; ++q)
                    reinterpret_cast<float4*>(nb)[half * 8 + q] =
                        make_float4(a0[4*q], a0[4*q+1], a0[4*q+2], a0[4*q+3]);
            } else {
#pragma unroll
                for (int q = 0; q < 8; ++q)
                    reinterpret_cast<float4*>(nb)[half * 8 + q] =
                        make_float4(a1[4*q], a1[4*q+1], a1[4*q+2], a1[4*q+3]);
            }
        }
        __syncthreads();
    }
    double det = pivot_product(s_pk);
    if (tid == 0) {
        float kap = vij_valid(det) ? ((float)(det / (double)(g_Vii32[i] + g_Vii32[j])))
                                   : f_inf();
        g_kappa[b] = kap;
        if (kap < f_inf()) atomicMin(&g_kmin_key, f2key(kap));
    }
}

// ---------------------------------------------------------------------------
// K5a: parallel candidate collection near the global fp32 kmin.
// ---------------------------------------------------------------------------
__global__ void k5a_select() {
    const float kmin = key2f(g_kmin_key);
    if (!(kmin < 3.0e38f)) return;
    const float thr = kmin + (fabsf(kmin) * 1e-3f + 1e-30f);
    const int b = blockIdx.x * 256 + threadIdx.x;
    if (g_kappa[b] <= thr) {
        int p = atomicAdd(&g_ncand, 1);
        if (p < 128) g_cand[p] = b;
    }
}

// ---------------------------------------------------------------------------
// K5b0: fp64 Vii for clusters referenced by candidates (lazy; few blocks).
// ---------------------------------------------------------------------------
__global__ void k5b0_vii(const float* __restrict__ S_in) {
    const int ncand = min(g_ncand, 128);
    const int t = blockIdx.x;
    if (t >= 2 * ncand) return;
    const int flat = g_cand[t >> 1];
    const int c = (t & 1) ? (flat & (NC - 1)) : (flat >> 7);
    const int tid = threadIdx.x;
    __shared__ double s_piv[128];
    __shared__ double s_inv[2];
    const double invn = 1.0 / (double)g_n[c];
    const float* Sc = S_eff(S_in, c);
    const int row = tid >> 1;
    const int c0  = (tid & 1) << 5;
    double a[32];
    const float* Sr = Sc + row * ND + c0;
#pragma unroll
    for (int q = 0; q < 32; ++q) a[q] = (double)Sr[q] * invn;
    double det = block_det64d(a, s_piv, s_inv);
    if (tid == 0) g_Vii64[c] = det;
}

// ---------------------------------------------------------------------------
// K5b: fp64 recompute of kappa for each candidate pair (same validity mask).
// ---------------------------------------------------------------------------
__global__ void k5b_refine() {
    const int b = blockIdx.x;
    const int ncand = min(g_ncand, 128);
    if (b >= ncand) return;
    const int tid = threadIdx.x;
    __shared__ double s_piv[128];
    __shared__ double s_inv[2];
    __shared__ double s_muij[64];
    const int flat = g_cand[b];
    const int i = flat >> 7;
    const int j = flat & (NC - 1);
    const double ni = (double)g_n[i], nj = (double)g_n[j];
    const double nij = ni + nj;
    if (tid < 64)
        s_muij[tid] = (ni * (double)g_mu[i * ND + tid] + nj * (double)g_mu[j * ND + tid]) / nij;
    __syncthreads();
    const double invs = 1.0 / (nij - 1.0);
    const int row = tid >> 1;
    const int c0  = (tid & 1) << 5;
    const double mr = s_muij[row];
    const float* zi = &g_ZZ[i * ND * ND + row * ND + c0];
    const float* zj = &g_ZZ[j * ND * ND + row * ND + c0];
    double a[32];
#pragma unroll
    for (int q = 0; q < 32; ++q)
        a[q] = ((double)zi[q] + (double)zj[q] - mr * s_muij[c0 + q]) * invs;
    double det = block_det64d(a, s_piv, s_inv);
    if (tid == 0)
        g_kval[b] = vij_valid(det) ? (det / (g_Vii64[i] + g_Vii64[j])) : d_inf();
}

// ---------------------------------------------------------------------------
// K5c: argmin over refined candidates (first-flat-index ties), conditional
// merge, write out = mu * active.
// ---------------------------------------------------------------------------
__global__ void k5c_final(float* __restrict__ out) {
    const int tid = threadIdx.x;   // 256
    __shared__ double s_val[256];
    __shared__ int    s_idx[256];
    const int ncand = min(g_ncand, 128);
    double bv = d_inf(); int bi = 0x7fffffff;
    for (int b = tid; b < ncand; b += 256) {
        double v = g_kval[b]; int fi = g_cand[b];
        if (v < bv || (v == bv && fi < bi)) { bv = v; bi = fi; }
    }
    s_val[tid] = bv; s_idx[tid] = bi;
    __syncthreads();
    for (int s = 128; s; s >>= 1) {
        if (tid < s) {
            double v2 = s_val[tid + s]; int i2 = s_idx[tid + s];
            if (v2 < s_val[tid] || (v2 == s_val[tid] && i2 < s_idx[tid])) {
                s_val[tid] = v2; s_idx[tid] = i2;
            }
        }
        __syncthreads();
    }
    __shared__ int s_mi, s_mj, s_do;
    __shared__ float s_nmi, s_nmj;
    if (tid == 0) {
        s_do = (s_val[0] < 0.9) ? 1 : 0;
        s_mi = s_idx[0] >> 7;
        s_mj = s_idx[0] & (NC - 1);
        if (s_do) { s_nmi = g_n[s_mi]; s_nmj = g_n[s_mj]; }
    }
    __syncthreads();
    if (s_do) {
        if (tid < 64) {
            const int mi = s_mi, mj = s_mj;
            g_mu[mi * ND + tid] =
                (s_nmi * g_mu[mi * ND + tid] + s_nmj * g_mu[mj * ND + tid]) / (s_nmi + s_nmj);
        }
        if (tid == 0) g_active[s_mj] = 0;
    }
    __syncthreads();
    for (int idx = tid; idx < NC * ND; idx += 256)
        out[idx] = g_active[idx >> 6] ? g_mu[idx] : 0.0f;
}

// ---------------------------------------------------------------------------
extern "C" void kernel_launch(void* const* d_in, const int* in_sizes, int n_in,
                              void* d_out, int out_size) {
    const float* z  = (const float*)d_in[0];
    const float* mu = (const float*)d_in[1];
    const float* S  = (const float*)d_in[2];
    const float* n  = (const float*)d_in[3];
    const int*   ca = (const int*)d_in[4];
    float* out = (float*)d_out;

    k1_gamma<<<NC, 128>>>(z, mu, S, n, ca);
    k2_update<<<1, 256>>>(z, S, ca);
    k3_fix<<<1, 128>>>();
    k4_pairs<<<NC * NC, 64>>>();
    k5a_select<<<64, 256>>>();
    k5b0_vii<<<256, 128>>>(S);
    k5b_refine<<<128, 128>>>();
    k5c_final<<<1, 256>>>(out);
}

// round 9
// speedup vs baseline: 1.5511x; 1.3549x over previous
#include <cuda_runtime.h>
#include <math.h>

#define NC 128   // clusters
#define ND 64    // dimension

// V_FACTOR = 2*pi^32/(64*31!) — reference multiplies det by this in fp32; the
// product underflows (FTZ -> 0) for tiny dets, which drives the validity mask.
#define V_FACTOR_D 3.080513e-20
#define FLT_MIN_NORMAL 1.1754943508222875e-38

// ---------------- device scratch (no allocations allowed) ----------------
static __device__ __align__(16) float g_mu[NC * ND];
static __device__ __align__(16) float g_Smod[ND * ND];   // the one mutated S row
static __device__ __align__(16) float g_ZZ[NC * ND * ND];
static __device__ float  g_n[NC];
static __device__ float  g_Gamma[NC];
static __device__ float  g_Vii32[NC];
static __device__ double g_Vii64[NC];
static __device__ float  g_kappa[NC * NC];
static __device__ int    g_active[NC];
static __device__ int    g_sel[NC];
static __device__ int    g_modidx;
static __device__ int    g_ncand;
static __device__ int    g_kmin_key;     // order-preserving int key of min kappa
static __device__ int    g_cand[128];
static __device__ double g_kval[128];

__device__ __forceinline__ float  f_inf() { return __int_as_float(0x7f800000); }
__device__ __forceinline__ double d_inf() { return __longlong_as_double(0x7ff0000000000000LL); }

__device__ __forceinline__ int f2key(float f) {
    int b = __float_as_int(f);
    return (b >= 0) ? b : (int)(~(unsigned)b);
}
__device__ __forceinline__ float key2f(int k) {
    return __int_as_float((k >= 0) ? k : (int)(~(unsigned)k));
}

// Emulate the reference's fp32 `V_ij = V_FACTOR*det > 0` test under FTZ.
__device__ __forceinline__ bool vij_valid(double det) {
    return (det > 0.0) && (det * V_FACTOR_D >= FLT_MIN_NORMAL);
}

// ---------------------------------------------------------------------------
// fp32 64x64 forward elimination (128-thread variant) — used by k1 / k23.
// row = tid>>1, half = tid&1 owns cols [32*half, +32). 1 barrier/step via
// double-buffered pivot rows. Pivots stashed to s_pk for post-loop reduction.
// ---------------------------------------------------------------------------
__device__ __forceinline__ void block_elim64f(float a[32], float* s_piv, float* s_pk) {
    const int tid  = threadIdx.x;
    const int row  = tid >> 1;
    const int half = tid & 1;
    const int c0   = half << 5;
    if (row == 0) {
#pragma unroll
        for (int q = 0; q < 8; ++q)
            reinterpret_cast<float4*>(s_piv)[half * 8 + q] =
                make_float4(a[4*q], a[4*q+1], a[4*q+2], a[4*q+3]);
    }
    __syncthreads();
#pragma unroll
    for (int k = 0; k < 64; ++k) {
        const float* buf = s_piv + ((k & 1) << 6);
        float pk = buf[k];
        if (tid == 0) s_pk[k] = pk;
        float cand  = a[k & 31];
        float other = __shfl_xor_sync(0xffffffffu, cand, 1);
        float fr    = ((k >> 5) == half) ? cand : other;
        float f     = __fdividef(fr, pk);
        if (row > k) {
#pragma unroll
            for (int q = 0; q < 8; ++q) {
                if (c0 + 4*q + 3 >= k) {
                    float4 p = reinterpret_cast<const float4*>(buf)[half * 8 + q];
                    a[4*q]   -= f * p.x;
                    a[4*q+1] -= f * p.y;
                    a[4*q+2] -= f * p.z;
                    a[4*q+3] -= f * p.w;
                }
            }
        }
        if (row == k + 1) {
            float* nb = s_piv + (((k + 1) & 1) << 6);
#pragma unroll
            for (int q = 0; q < 8; ++q)
                reinterpret_cast<float4*>(nb)[half * 8 + q] =
                    make_float4(a[4*q], a[4*q+1], a[4*q+2], a[4*q+3]);
        }
        __syncthreads();
    }
}

// Warp-0 product of the 64 stashed pivots (result on thread 0).
__device__ __forceinline__ double pivot_product(const float* s_pk) {
    const int tid = threadIdx.x;
    double v = 1.0;
    if (tid < 32) {
        v = (double)s_pk[tid] * (double)s_pk[tid + 32];
#pragma unroll
        for (int off = 16; off; off >>= 1)
            v *= __shfl_down_sync(0xffffffffu, v, off);
    }
    return v;
}

// ---------------------------------------------------------------------------
// fp64 single-step engine — only candidate refinement (few blocks).
// ---------------------------------------------------------------------------
__device__ __forceinline__ double block_det64d(double a[32], double* s_piv, double* s_inv) {
    const int tid  = threadIdx.x;
    const int row  = tid >> 1;
    const int half = tid & 1;
    const int c0   = half << 5;
    if (row == 0) {
#pragma unroll
        for (int q = 0; q < 16; ++q)
            reinterpret_cast<double2*>(s_piv)[half * 16 + q] = make_double2(a[2*q], a[2*q+1]);
        if (tid == 0) s_inv[0] = 1.0 / a[0];
    }
    __syncthreads();
    double det = 1.0;
#pragma unroll
    for (int k = 0; k < 64; ++k) {
        const double* buf = s_piv + ((k & 1) << 6);
        double pk  = buf[k];
        double ipk = s_inv[k & 1];
        if (tid == 0) det *= pk;
        double cand  = a[k & 31];
        double other = __shfl_xor_sync(0xffffffffu, cand, 1);
        double fr    = ((k >> 5) == half) ? cand : other;
        double f     = fr * ipk;
        if (row > k) {
#pragma unroll
            for (int q = 0; q < 16; ++q) {
                if (c0 + 2*q + 1 >= k) {
                    double2 p = reinterpret_cast<const double2*>(buf)[half * 16 + q];
                    a[2*q]   -= f * p.x;
                    a[2*q+1] -= f * p.y;
                }
            }
        }
        if (row == k + 1) {
            double* nb = s_piv + (((k + 1) & 1) << 6);
#pragma unroll
            for (int q = 0; q < 16; ++q)
                reinterpret_cast<double2*>(nb)[half * 16 + q] = make_double2(a[2*q], a[2*q+1]);
            if (((k + 1) >> 5) == half) s_inv[(k + 1) & 1] = 1.0 / a[(k + 1) & 31];
        }
        __syncthreads();
    }
    return det;
}

// ---------------------------------------------------------------------------
// K1 (merged k0+k1+k3): init state, ZZ build, Vii32, Gamma.
// ---------------------------------------------------------------------------
__global__ void __launch_bounds__(128, 6)
k1_gamma(const float* __restrict__ z, const float* __restrict__ mu_in,
         const float* __restrict__ S_in, const float* __restrict__ n_in,
         const int* __restrict__ cact) {
    const int c = blockIdx.x;
    const int tid = threadIdx.x;
    __shared__ float s_piv[128];
    __shared__ float s_pk[64];
    __shared__ float s_x[64];
    __shared__ float s_e[64];
    const float nc = n_in[c];
    if (tid < 64) {
        float m = mu_in[c * ND + tid];
        g_mu[c * ND + tid] = m;
        float e = z[tid] - m;
        s_e[tid] = e;
        s_x[tid] = e;
    }
    if (tid == 0) {
        g_n[c] = nc;
        g_active[c] = (c < cact[0]) ? 1 : 0;
        if (c == 0) { g_kmin_key = 0x7f800000; g_ncand = 0; }
    }
    // ZZ build from INPUT S, mu (k23 patches the one mutated cluster)
    {
        const float coef = (nc - 1.0f) / nc;
        const float* mc = mu_in + c * ND;
        const float4* Sc4 = reinterpret_cast<const float4*>(S_in + c * ND * ND);
        const float4* mc4 = reinterpret_cast<const float4*>(mc);
        float4* Z4 = reinterpret_cast<float4*>(&g_ZZ[c * ND * ND]);
        for (int t = tid; t < ND * ND / 4; t += 128) {
            float4 s = Sc4[t];
            float4 m = mc4[t & 15];
            float mr = mc[t >> 4];
            Z4[t] = make_float4(coef * s.x + mr * m.x, coef * s.y + mr * m.y,
                                coef * s.z + mr * m.z, coef * s.w + mr * m.w);
        }
    }
    // elimination on S/n with RHS solve
    const float invn = 1.0f / nc;
    const int row  = tid >> 1;
    const int half = tid & 1;
    const int c0   = half << 5;
    float a[32];
    {
        const float4* Sr = reinterpret_cast<const float4*>(S_in + c * ND * ND + row * ND + c0);
#pragma unroll
        for (int q = 0; q < 8; ++q) {
            float4 v = Sr[q];
            a[4*q]   = v.x * invn;
            a[4*q+1] = v.y * invn;
            a[4*q+2] = v.z * invn;
            a[4*q+3] = v.w * invn;
        }
    }
    if (row == 0) {
#pragma unroll
        for (int q = 0; q < 8; ++q)
            reinterpret_cast<float4*>(s_piv)[half * 8 + q] =
                make_float4(a[4*q], a[4*q+1], a[4*q+2], a[4*q+3]);
    }
    __syncthreads();
#pragma unroll
    for (int k = 0; k < 64; ++k) {
        const float* buf = s_piv + ((k & 1) << 6);
        float pk = buf[k];
        float xk = s_x[k];
        if (tid == 0) s_pk[k] = pk;
        float cand  = a[k & 31];
        float other = __shfl_xor_sync(0xffffffffu, cand, 1);
        float fr    = ((k >> 5) == half) ? cand : other;
        float f     = __fdividef(fr, pk);
        if (row > k) {
#pragma unroll
            for (int q = 0; q < 8; ++q) {
                if (c0 + 4*q + 3 >= k) {
                    float4 p = reinterpret_cast<const float4*>(buf)[half * 8 + q];
                    a[4*q]   -= f * p.x;
                    a[4*q+1] -= f * p.y;
                    a[4*q+2] -= f * p.z;
                    a[4*q+3] -= f * p.w;
                }
            }
            if (half == 0) s_x[row] -= f * xk;   // one writer per row
        }
        if (row == k + 1) {
            float* nb = s_piv + (((k + 1) & 1) << 6);
#pragma unroll
            for (int q = 0; q < 8; ++q)
                reinterpret_cast<float4*>(nb)[half * 8 + q] =
                    make_float4(a[4*q], a[4*q+1], a[4*q+2], a[4*q+3]);
        }
        __syncthreads();
    }
    // post-loop reductions (warp 0): d2_euc, d2_mah, det
    if (tid < 32) {
        float e0 = s_e[tid], e1 = s_e[tid + 32];
        float x0 = s_x[tid], x1 = s_x[tid + 32];
        float p0 = s_pk[tid], p1 = s_pk[tid + 32];
        float deuc = e0 * e0 + e1 * e1;
        double dmah = (double)(x0 * x0) / (double)p0 + (double)(x1 * x1) / (double)p1;
        double dprod = (double)p0 * (double)p1;
#pragma unroll
        for (int off = 16; off; off >>= 1) {
            deuc  += __shfl_down_sync(0xffffffffu, deuc, off);
            dmah  += __shfl_down_sync(0xffffffffu, dmah, off);
            dprod *= __shfl_down_sync(0xffffffffu, dprod, off);
        }
        if (tid == 0) {
            float d2 = (nc < 100.0f) ? deuc : (float)dmah;
            g_Gamma[c] = (c < cact[0]) ? expf(-d2) : 0.0f;
            g_Vii32[c] = (float)dprod;
        }
    }
}

// ---------------------------------------------------------------------------
// K23 (merged k2_update + k3_fix), 128 threads, 1 block:
//  - warp-parallel argmax Gamma (first-index ties)
//  - incremental update of winner or spawn (S mutation -> g_Smod + g_modidx)
//  - sel flags
//  - rebuild ZZ + Vii32 for the mutated cluster
// ---------------------------------------------------------------------------
__global__ void __launch_bounds__(128, 6)
k23_update_fix(const float* __restrict__ z, const float* __restrict__ S_in,
               const int* __restrict__ cact) {
    const int tid = threadIdx.x;   // 128
    __shared__ float s_ej[64];
    __shared__ float s_piv[128];
    __shared__ float s_pk[64];
    __shared__ int s_j, s_incr, s_c;
    __shared__ float s_nj;
    if (tid < 32) {
        float bv = g_Gamma[tid]; int bi = tid;
#pragma unroll
        for (int t = 1; t < 4; ++t) {
            float v = g_Gamma[tid + 32 * t];
            if (v > bv) { bv = v; bi = tid + 32 * t; }   // increasing idx: strict >
        }
#pragma unroll
        for (int off = 16; off; off >>= 1) {
            float ov = __shfl_down_sync(0xffffffffu, bv, off);
            int   oi = __shfl_down_sync(0xffffffffu, bi, off);
            if (ov > bv || (ov == bv && oi < bi)) { bv = ov; bi = oi; }
        }
        if (tid == 0) {
            s_j = bi;
            s_incr = (bv > 0.9f) ? 1 : 0;
            s_nj = g_n[bi];
        }
    }
    __syncthreads();
    if (s_incr) {
        const int j = s_j;
        if (tid < 64) s_ej[tid] = z[tid] - g_mu[j * ND + tid];
        __syncthreads();
        if (tid < 64) g_mu[j * ND + tid] += s_ej[tid] / (1.0f + s_nj);
        for (int idx = tid; idx < ND * ND; idx += 128)
            g_Smod[idx] = S_in[j * ND * ND + idx] + s_ej[idx >> 6] * s_ej[idx & 63];
        if (tid == 0) { g_n[j] = s_nj + 1.0f; g_modidx = j; s_c = j; }
    } else {
        const int ca = cact[0];
        if (tid < 64) g_mu[ca * ND + tid] = z[tid];
        for (int idx = tid; idx < ND * ND; idx += 128)
            g_Smod[idx] = ((idx >> 6) == (idx & 63)) ? 1.0f : 0.0f;
        if (tid == 0) { g_n[ca] = 1.0f; g_Gamma[ca] = 1.0f; g_active[ca] = 1;
                        g_modidx = ca; s_c = ca; }
    }
    __syncthreads();
    if (tid < NC)
        g_sel[tid] = (g_Gamma[tid] > 0.225f && g_active[tid]) ? 1 : 0;
    __syncthreads();
    // ---- k3_fix part: rebuild ZZ + Vii32 for cluster s_c from g_Smod ----
    const int c = s_c;
    const float nc   = g_n[c];
    const float coef = (nc - 1.0f) / nc;
    const float invn = 1.0f / nc;
    const float* mc = &g_mu[c * ND];
    const float4* Sc4 = reinterpret_cast<const float4*>(g_Smod);
    const float4* mc4 = reinterpret_cast<const float4*>(mc);
    float4* Z4 = reinterpret_cast<float4*>(&g_ZZ[c * ND * ND]);
    for (int t = tid; t < ND * ND / 4; t += 128) {
        float4 s = Sc4[t];
        float4 m = mc4[t & 15];
        float mr = mc[t >> 4];
        Z4[t] = make_float4(coef * s.x + mr * m.x, coef * s.y + mr * m.y,
                            coef * s.z + mr * m.z, coef * s.w + mr * m.w);
    }
    const int row = tid >> 1;
    const int c0  = (tid & 1) << 5;
    float a[32];
    const float4* Sr = reinterpret_cast<const float4*>(g_Smod + row * ND + c0);
#pragma unroll
    for (int q = 0; q < 8; ++q) {
        float4 v = Sr[q];
        a[4*q]   = v.x * invn;
        a[4*q+1] = v.y * invn;
        a[4*q+2] = v.z * invn;
        a[4*q+3] = v.w * invn;
    }
    __syncthreads();
    block_elim64f(a, s_piv, s_pk);
    double det = pivot_product(s_pk);
    if (tid == 0) g_Vii32[c] = (float)det;
}

// ---------------------------------------------------------------------------
// K4 (SCREEN, LDL^T): 64 threads/block. Thread t: r2 = t&31, h = t>>5
// (warp 0 = cols 0-31, warp 1 = cols 32-63 -> warp-uniform chunk predicates).
// Rows (r2, r2+32). Only the pivot COLUMN is broadcast (double-buffered
// s_col); multiplier f_r = col[r] * (1/d) — no shfl. Update is the outer
// product col x col on the lower triangle; upper-triangle register slots
// receive garbage that is provably never read (cols <= k are only read at
// their publish step, which precedes any boundary-chunk corruption).
// det = prod d_k.
// ---------------------------------------------------------------------------
__global__ void __launch_bounds__(64, 8)
k4_pairs() {
    const int b = blockIdx.x;
    const int i = b >> 7;
    const int j = b & (NC - 1);
    const int tid = threadIdx.x;   // 64
    if (i >= j || !g_sel[i] || !g_sel[j]) {
        if (tid == 0) g_kappa[b] = f_inf();
        return;
    }
    __shared__ __align__(16) float s_col[2][64];
    __shared__ float s_pk[64];
    __shared__ float s_muij[64];
    const float ni = g_n[i], nj = g_n[j];
    const float nij = ni + nj;
    s_muij[tid] = (ni * g_mu[i * ND + tid] + nj * g_mu[j * ND + tid]) / nij;
    __syncthreads();
    const float invs = 1.0f / (nij - 1.0f);
    const int r2 = tid & 31;
    const int h  = tid >> 5;          // warp-uniform
    const int c0 = h << 5;
    const int rA = r2, rB = r2 + 32;
    float aA[32], aB[32];
    // row rB (always carries lower-triangle data in both halves)
    {
        const float mrB = s_muij[rB];
        const float4* zi4 = reinterpret_cast<const float4*>(&g_ZZ[i * ND * ND + rB * ND + c0]);
        const float4* zj4 = reinterpret_cast<const float4*>(&g_ZZ[j * ND * ND + rB * ND + c0]);
#pragma unroll
        for (int q = 0; q < 8; ++q) {
            float4 x = zi4[q], y = zj4[q];
            aB[4*q]   = (x.x + y.x - mrB * s_muij[c0 + 4*q])     * invs;
            aB[4*q+1] = (x.y + y.y - mrB * s_muij[c0 + 4*q + 1]) * invs;
            aB[4*q+2] = (x.z + y.z - mrB * s_muij[c0 + 4*q + 2]) * invs;
            aB[4*q+3] = (x.w + y.w - mrB * s_muij[c0 + 4*q + 3]) * invs;
        }
    }
    // row rA: lower part lives entirely in half 0 (rA <= 31)
    if (h == 0) {
        const float mrA = s_muij[rA];
        const float4* zi4 = reinterpret_cast<const float4*>(&g_ZZ[i * ND * ND + rA * ND]);
        const float4* zj4 = reinterpret_cast<const float4*>(&g_ZZ[j * ND * ND + rA * ND]);
#pragma unroll
        for (int q = 0; q < 8; ++q) {
            float4 x = zi4[q], y = zj4[q];
            aA[4*q]   = (x.x + y.x - mrA * s_muij[4*q])     * invs;
            aA[4*q+1] = (x.y + y.y - mrA * s_muij[4*q + 1]) * invs;
            aA[4*q+2] = (x.z + y.z - mrA * s_muij[4*q + 2]) * invs;
            aA[4*q+3] = (x.w + y.w - mrA * s_muij[4*q + 3]) * invs;
        }
        // initial publish: column 0 (elements (r,0) live in half 0)
        s_col[0][rA] = aA[0];
        s_col[0][rB] = aB[0];
    }
    __syncthreads();
#pragma unroll
    for (int k = 0; k < 64; ++k) {
        const float* cur = s_col[k & 1];
        const float d = cur[k];
        if (tid == 0) s_pk[k] = d;
        const float invd = __fdividef(1.0f, d);
        const float fA = cur[rA] * invd;
        const float fB = cur[rB] * invd;
        const bool uA = (h == 0) && (rA > k);
        const bool uB = (rB > k);
#pragma unroll
        for (int q = 0; q < 8; ++q) {
            if (c0 + 4*q + 3 > k) {        // warp-uniform live-chunk test
                float4 v = *reinterpret_cast<const float4*>(&cur[c0 + 4*q]);
                if (uA) {
                    aA[4*q]   -= fA * v.x;
                    aA[4*q+1] -= fA * v.y;
                    aA[4*q+2] -= fA * v.z;
                    aA[4*q+3] -= fA * v.w;
                }
                if (uB) {
                    aB[4*q]   -= fB * v.x;
                    aB[4*q+1] -= fB * v.y;
                    aB[4*q+2] -= fB * v.z;
                    aB[4*q+3] -= fB * v.w;
                }
            }
        }
        // publish column k+1 (post-update values) into the alternate buffer
        if (k < 63) {
            const int kk = k + 1;
            if ((kk >> 5) == h) {          // warp-uniform
                float* nxt = s_col[kk & 1];
                const int idx = kk & 31;   // static per unrolled k
                if (h == 0 && rA >= kk) nxt[rA] = aA[idx];
                if (rB >= kk)           nxt[rB] = aB[idx];
            }
        }
        __syncthreads();
    }
    double det = pivot_product(s_pk);
    if (tid == 0) {
        float kap = vij_valid(det) ? ((float)(det / (double)(g_Vii32[i] + g_Vii32[j])))
                                   : f_inf();
        g_kappa[b] = kap;
        if (kap < f_inf()) atomicMin(&g_kmin_key, f2key(kap));
    }
}

// ---------------------------------------------------------------------------
// K5a: parallel candidate collection near the global fp32 kmin.
// ---------------------------------------------------------------------------
__global__ void k5a_select() {
    const float kmin = key2f(g_kmin_key);
    if (!(kmin < 3.0e38f)) return;
    const float thr = kmin + (fabsf(kmin) * 1e-3f + 1e-30f);
    const int b = blockIdx.x * 256 + threadIdx.x;
    if (g_kappa[b] <= thr) {
        int p = atomicAdd(&g_ncand, 1);
        if (p < 128) g_cand[p] = b;
    }
}

// ---------------------------------------------------------------------------
// K5b0: fp64 Vii for clusters referenced by candidates (lazy; few blocks).
// ---------------------------------------------------------------------------
__global__ void k5b0_vii(const float* __restrict__ S_in) {
    const int ncand = min(g_ncand, 128);
    const int t = blockIdx.x;
    if (t >= 2 * ncand) return;
    const int flat = g_cand[t >> 1];
    const int c = (t & 1) ? (flat & (NC - 1)) : (flat >> 7);
    const int tid = threadIdx.x;
    __shared__ double s_piv[128];
    __shared__ double s_inv[2];
    const double invn = 1.0 / (double)g_n[c];
    const float* Sc = (c == g_modidx) ? g_Smod : (S_in + c * ND * ND);
    const int row = tid >> 1;
    const int c0  = (tid & 1) << 5;
    double a[32];
    const float* Sr = Sc + row * ND + c0;
#pragma unroll
    for (int q = 0; q < 32; ++q) a[q] = (double)Sr[q] * invn;
    double det = block_det64d(a, s_piv, s_inv);
    if (tid == 0) g_Vii64[c] = det;
}

// ---------------------------------------------------------------------------
// K5b: fp64 recompute of kappa for each candidate pair (same validity mask).
// ---------------------------------------------------------------------------
__global__ void k5b_refine() {
    const int b = blockIdx.x;
    const int ncand = min(g_ncand, 128);
    if (b >= ncand) return;
    const int tid = threadIdx.x;
    __shared__ double s_piv[128];
    __shared__ double s_inv[2];
    __shared__ double s_muij[64];
    const int flat = g_cand[b];
    const int i = flat >> 7;
    const int j = flat & (NC - 1);
    const double ni = (double)g_n[i], nj = (double)g_n[j];
    const double nij = ni + nj;
    if (tid < 64)
        s_muij[tid] = (ni * (double)g_mu[i * ND + tid] + nj * (double)g_mu[j * ND + tid]) / nij;
    __syncthreads();
    const double invs = 1.0 / (nij - 1.0);
    const int row = tid >> 1;
    const int c0  = (tid & 1) << 5;
    const double mr = s_muij[row];
    const float* zi = &g_ZZ[i * ND * ND + row * ND + c0];
    const float* zj = &g_ZZ[j * ND * ND + row * ND + c0];
    double a[32];
#pragma unroll
    for (int q = 0; q < 32; ++q)
        a[q] = ((double)zi[q] + (double)zj[q] - mr * s_muij[c0 + q]) * invs;
    double det = block_det64d(a, s_piv, s_inv);
    if (tid == 0)
        g_kval[b] = vij_valid(det) ? (det / (g_Vii64[i] + g_Vii64[j])) : d_inf();
}

// ---------------------------------------------------------------------------
// K5c: argmin over refined candidates (first-flat-index ties), conditional
// merge, write out = mu * active.
// ---------------------------------------------------------------------------
__global__ void k5c_final(float* __restrict__ out) {
    const int tid = threadIdx.x;   // 256
    __shared__ double s_val[256];
    __shared__ int    s_idx[256];
    const int ncand = min(g_ncand, 128);
    double bv = d_inf(); int bi = 0x7fffffff;
    for (int b = tid; b < ncand; b += 256) {
        double v = g_kval[b]; int fi = g_cand[b];
        if (v < bv || (v == bv && fi < bi)) { bv = v; bi = fi; }
    }
    s_val[tid] = bv; s_idx[tid] = bi;
    __syncthreads();
    for (int s = 128; s; s >>= 1) {
        if (tid < s) {
            double v2 = s_val[tid + s]; int i2 = s_idx[tid + s];
            if (v2 < s_val[tid] || (v2 == s_val[tid] && i2 < s_idx[tid])) {
                s_val[tid] = v2; s_idx[tid] = i2;
            }
        }
        __syncthreads();
    }
    __shared__ int s_mi, s_mj, s_do;
    __shared__ float s_nmi, s_nmj;
    if (tid == 0) {
        s_do = (s_val[0] < 0.9) ? 1 : 0;
        s_mi = s_idx[0] >> 7;
        s_mj = s_idx[0] & (NC - 1);
        if (s_do) { s_nmi = g_n[s_mi]; s_nmj = g_n[s_mj]; }
    }
    __syncthreads();
    if (s_do) {
        if (tid < 64) {
            const int mi = s_mi, mj = s_mj;
            g_mu[mi * ND + tid] =
                (s_nmi * g_mu[mi * ND + tid] + s_nmj * g_mu[mj * ND + tid]) / (s_nmi + s_nmj);
        }
        if (tid == 0) g_active[s_mj] = 0;
    }
    __syncthreads();
    for (int idx = tid; idx < NC * ND; idx += 256)
        out[idx] = g_active[idx >> 6] ? g_mu[idx] : 0.0f;
}

// ---------------------------------------------------------------------------
extern "C" void kernel_launch(void* const* d_in, const int* in_sizes, int n_in,
                              void* d_out, int out_size) {
    const float* z  = (const float*)d_in[0];
    const float* mu = (const float*)d_in[1];
    const float* S  = (const float*)d_in[2];
    const float* n  = (const float*)d_in[3];
    const int*   ca = (const int*)d_in[4];
    float* out = (float*)d_out;

    k1_gamma<<<NC, 128>>>(z, mu, S, n, ca);
    k23_update_fix<<<1, 128>>>(z, S, ca);
    k4_pairs<<<NC * NC, 64>>>();
    k5a_select<<<64, 256>>>();
    k5b0_vii<<<256, 128>>>(S);
    k5b_refine<<<128, 128>>>();
    k5c_final<<<1, 256>>>(out);
}

// round 10
// speedup vs baseline: 1.6030x; 1.0334x over previous
#include <cuda_runtime.h>
#include <math.h>

#define NC 128   // clusters
#define ND 64    // dimension

// V_FACTOR = 2*pi^32/(64*31!) — reference multiplies det by this in fp32; the
// product underflows (FTZ -> 0) for tiny dets, which drives the validity mask.
#define V_FACTOR_D 3.080513e-20
#define FLT_MIN_NORMAL 1.1754943508222875e-38

// ---------------- device scratch (no allocations allowed) ----------------
static __device__ __align__(16) float g_mu[NC * ND];
static __device__ __align__(16) float g_Smod[ND * ND];   // the one mutated S row
static __device__ __align__(16) float g_ZZ[NC * ND * ND];
static __device__ float  g_n[NC];
static __device__ float  g_Gamma[NC];
static __device__ float  g_Vii32[NC];
static __device__ double g_Vii64[NC];
static __device__ float  g_kappa[NC * NC];
static __device__ int    g_active[NC];
static __device__ int    g_sel[NC];
static __device__ int    g_modidx;
static __device__ int    g_ncand;
static __device__ int    g_kmin_key;     // order-preserving int key of min kappa
static __device__ int    g_cand[128];
static __device__ double g_kval[128];

__device__ __forceinline__ float  f_inf() { return __int_as_float(0x7f800000); }
__device__ __forceinline__ double d_inf() { return __longlong_as_double(0x7ff0000000000000LL); }

__device__ __forceinline__ int f2key(float f) {
    int b = __float_as_int(f);
    return (b >= 0) ? b : (int)(~(unsigned)b);
}
__device__ __forceinline__ float key2f(int k) {
    return __int_as_float((k >= 0) ? k : (int)(~(unsigned)k));
}

// Emulate the reference's fp32 `V_ij = V_FACTOR*det > 0` test under FTZ.
__device__ __forceinline__ bool vij_valid(double det) {
    return (det > 0.0) && (det * V_FACTOR_D >= FLT_MIN_NORMAL);
}

// ---------------------------------------------------------------------------
// fp32 64x64 forward elimination (128-thread variant) — used by k1 / k23.
// row = tid>>1, half = tid&1 owns cols [32*half, +32). 1 barrier/step via
// double-buffered pivot rows. Pivots stashed to s_pk for post-loop reduction.
// ---------------------------------------------------------------------------
__device__ __forceinline__ void block_elim64f(float a[32], float* s_piv, float* s_pk) {
    const int tid  = threadIdx.x;
    const int row  = tid >> 1;
    const int half = tid & 1;
    const int c0   = half << 5;
    if (row == 0) {
#pragma unroll
        for (int q = 0; q < 8; ++q)
            reinterpret_cast<float4*>(s_piv)[half * 8 + q] =
                make_float4(a[4*q], a[4*q+1], a[4*q+2], a[4*q+3]);
    }
    __syncthreads();
#pragma unroll
    for (int k = 0; k < 64; ++k) {
        const float* buf = s_piv + ((k & 1) << 6);
        float pk = buf[k];
        if (tid == 0) s_pk[k] = pk;
        float cand  = a[k & 31];
        float other = __shfl_xor_sync(0xffffffffu, cand, 1);
        float fr    = ((k >> 5) == half) ? cand : other;
        float f     = __fdividef(fr, pk);
        if (row > k) {
#pragma unroll
            for (int q = 0; q < 8; ++q) {
                if (c0 + 4*q + 3 >= k) {
                    float4 p = reinterpret_cast<const float4*>(buf)[half * 8 + q];
                    a[4*q]   -= f * p.x;
                    a[4*q+1] -= f * p.y;
                    a[4*q+2] -= f * p.z;
                    a[4*q+3] -= f * p.w;
                }
            }
        }
        if (row == k + 1) {
            float* nb = s_piv + (((k + 1) & 1) << 6);
#pragma unroll
            for (int q = 0; q < 8; ++q)
                reinterpret_cast<float4*>(nb)[half * 8 + q] =
                    make_float4(a[4*q], a[4*q+1], a[4*q+2], a[4*q+3]);
        }
        __syncthreads();
    }
}

// Warp-0 product of the 64 stashed pivots (result on thread 0).
__device__ __forceinline__ double pivot_product(const float* s_pk) {
    const int tid = threadIdx.x;
    double v = 1.0;
    if (tid < 32) {
        v = (double)s_pk[tid] * (double)s_pk[tid + 32];
#pragma unroll
        for (int off = 16; off; off >>= 1)
            v *= __shfl_down_sync(0xffffffffu, v, off);
    }
    return v;
}

// ---------------------------------------------------------------------------
// fp64 single-step engine — only candidate refinement (few blocks).
// ---------------------------------------------------------------------------
__device__ __forceinline__ double block_det64d(double a[32], double* s_piv, double* s_inv) {
    const int tid  = threadIdx.x;
    const int row  = tid >> 1;
    const int half = tid & 1;
    const int c0   = half << 5;
    if (row == 0) {
#pragma unroll
        for (int q = 0; q < 16; ++q)
            reinterpret_cast<double2*>(s_piv)[half * 16 + q] = make_double2(a[2*q], a[2*q+1]);
        if (tid == 0) s_inv[0] = 1.0 / a[0];
    }
    __syncthreads();
    double det = 1.0;
#pragma unroll
    for (int k = 0; k < 64; ++k) {
        const double* buf = s_piv + ((k & 1) << 6);
        double pk  = buf[k];
        double ipk = s_inv[k & 1];
        if (tid == 0) det *= pk;
        double cand  = a[k & 31];
        double other = __shfl_xor_sync(0xffffffffu, cand, 1);
        double fr    = ((k >> 5) == half) ? cand : other;
        double f     = fr * ipk;
        if (row > k) {
#pragma unroll
            for (int q = 0; q < 16; ++q) {
                if (c0 + 2*q + 1 >= k) {
                    double2 p = reinterpret_cast<const double2*>(buf)[half * 16 + q];
                    a[2*q]   -= f * p.x;
                    a[2*q+1] -= f * p.y;
                }
            }
        }
        if (row == k + 1) {
            double* nb = s_piv + (((k + 1) & 1) << 6);
#pragma unroll
            for (int q = 0; q < 16; ++q)
                reinterpret_cast<double2*>(nb)[half * 16 + q] = make_double2(a[2*q], a[2*q+1]);
            if (((k + 1) >> 5) == half) s_inv[(k + 1) & 1] = 1.0 / a[(k + 1) & 31];
        }
        __syncthreads();
    }
    return det;
}

// ---------------------------------------------------------------------------
// K1 (merged k0+k1+k3): init state, ZZ build, Vii32, Gamma.
// ---------------------------------------------------------------------------
__global__ void __launch_bounds__(128, 6)
k1_gamma(const float* __restrict__ z, const float* __restrict__ mu_in,
         const float* __restrict__ S_in, const float* __restrict__ n_in,
         const int* __restrict__ cact) {
    const int c = blockIdx.x;
    const int tid = threadIdx.x;
    __shared__ float s_piv[128];
    __shared__ float s_pk[64];
    __shared__ float s_x[64];
    __shared__ float s_e[64];
    const float nc = n_in[c];
    if (tid < 64) {
        float m = mu_in[c * ND + tid];
        g_mu[c * ND + tid] = m;
        float e = z[tid] - m;
        s_e[tid] = e;
        s_x[tid] = e;
    }
    if (tid == 0) {
        g_n[c] = nc;
        g_active[c] = (c < cact[0]) ? 1 : 0;
        if (c == 0) { g_kmin_key = 0x7f800000; g_ncand = 0; }
    }
    // ZZ build from INPUT S, mu (k23 patches the one mutated cluster)
    {
        const float coef = (nc - 1.0f) / nc;
        const float* mc = mu_in + c * ND;
        const float4* Sc4 = reinterpret_cast<const float4*>(S_in + c * ND * ND);
        const float4* mc4 = reinterpret_cast<const float4*>(mc);
        float4* Z4 = reinterpret_cast<float4*>(&g_ZZ[c * ND * ND]);
        for (int t = tid; t < ND * ND / 4; t += 128) {
            float4 s = Sc4[t];
            float4 m = mc4[t & 15];
            float mr = mc[t >> 4];
            Z4[t] = make_float4(coef * s.x + mr * m.x, coef * s.y + mr * m.y,
                                coef * s.z + mr * m.z, coef * s.w + mr * m.w);
        }
    }
    // elimination on S/n with RHS solve
    const float invn = 1.0f / nc;
    const int row  = tid >> 1;
    const int half = tid & 1;
    const int c0   = half << 5;
    float a[32];
    {
        const float4* Sr = reinterpret_cast<const float4*>(S_in + c * ND * ND + row * ND + c0);
#pragma unroll
        for (int q = 0; q < 8; ++q) {
            float4 v = Sr[q];
            a[4*q]   = v.x * invn;
            a[4*q+1] = v.y * invn;
            a[4*q+2] = v.z * invn;
            a[4*q+3] = v.w * invn;
        }
    }
    if (row == 0) {
#pragma unroll
        for (int q = 0; q < 8; ++q)
            reinterpret_cast<float4*>(s_piv)[half * 8 + q] =
                make_float4(a[4*q], a[4*q+1], a[4*q+2], a[4*q+3]);
    }
    __syncthreads();
#pragma unroll
    for (int k = 0; k < 64; ++k) {
        const float* buf = s_piv + ((k & 1) << 6);
        float pk = buf[k];
        float xk = s_x[k];
        if (tid == 0) s_pk[k] = pk;
        float cand  = a[k & 31];
        float other = __shfl_xor_sync(0xffffffffu, cand, 1);
        float fr    = ((k >> 5) == half) ? cand : other;
        float f     = __fdividef(fr, pk);
        if (row > k) {
#pragma unroll
            for (int q = 0; q < 8; ++q) {
                if (c0 + 4*q + 3 >= k) {
                    float4 p = reinterpret_cast<const float4*>(buf)[half * 8 + q];
                    a[4*q]   -= f * p.x;
                    a[4*q+1] -= f * p.y;
                    a[4*q+2] -= f * p.z;
                    a[4*q+3] -= f * p.w;
                }
            }
            if (half == 0) s_x[row] -= f * xk;   // one writer per row
        }
        if (row == k + 1) {
            float* nb = s_piv + (((k + 1) & 1) << 6);
#pragma unroll
            for (int q = 0; q < 8; ++q)
                reinterpret_cast<float4*>(nb)[half * 8 + q] =
                    make_float4(a[4*q], a[4*q+1], a[4*q+2], a[4*q+3]);
        }
        __syncthreads();
    }
    // post-loop reductions (warp 0): d2_euc, d2_mah, det
    if (tid < 32) {
        float e0 = s_e[tid], e1 = s_e[tid + 32];
        float x0 = s_x[tid], x1 = s_x[tid + 32];
        float p0 = s_pk[tid], p1 = s_pk[tid + 32];
        float deuc = e0 * e0 + e1 * e1;
        double dmah = (double)(x0 * x0) / (double)p0 + (double)(x1 * x1) / (double)p1;
        double dprod = (double)p0 * (double)p1;
#pragma unroll
        for (int off = 16; off; off >>= 1) {
            deuc  += __shfl_down_sync(0xffffffffu, deuc, off);
            dmah  += __shfl_down_sync(0xffffffffu, dmah, off);
            dprod *= __shfl_down_sync(0xffffffffu, dprod, off);
        }
        if (tid == 0) {
            float d2 = (nc < 100.0f) ? deuc : (float)dmah;
            g_Gamma[c] = (c < cact[0]) ? expf(-d2) : 0.0f;
            g_Vii32[c] = (float)dprod;
        }
    }
}

// ---------------------------------------------------------------------------
// K23 (merged k2_update + k3_fix), 128 threads, 1 block:
//  - warp-parallel argmax Gamma (first-index ties)
//  - incremental update of winner or spawn (S mutation -> g_Smod + g_modidx)
//  - sel flags
//  - rebuild ZZ + Vii32 for the mutated cluster
// ---------------------------------------------------------------------------
__global__ void __launch_bounds__(128, 6)
k23_update_fix(const float* __restrict__ z, const float* __restrict__ S_in,
               const int* __restrict__ cact) {
    const int tid = threadIdx.x;   // 128
    __shared__ float s_ej[64];
    __shared__ float s_piv[128];
    __shared__ float s_pk[64];
    __shared__ int s_j, s_incr, s_c;
    __shared__ float s_nj;
    if (tid < 32) {
        float bv = g_Gamma[tid]; int bi = tid;
#pragma unroll
        for (int t = 1; t < 4; ++t) {
            float v = g_Gamma[tid + 32 * t];
            if (v > bv) { bv = v; bi = tid + 32 * t; }   // increasing idx: strict >
        }
#pragma unroll
        for (int off = 16; off; off >>= 1) {
            float ov = __shfl_down_sync(0xffffffffu, bv, off);
            int   oi = __shfl_down_sync(0xffffffffu, bi, off);
            if (ov > bv || (ov == bv && oi < bi)) { bv = ov; bi = oi; }
        }
        if (tid == 0) {
            s_j = bi;
            s_incr = (bv > 0.9f) ? 1 : 0;
            s_nj = g_n[bi];
        }
    }
    __syncthreads();
    if (s_incr) {
        const int j = s_j;
        if (tid < 64) s_ej[tid] = z[tid] - g_mu[j * ND + tid];
        __syncthreads();
        if (tid < 64) g_mu[j * ND + tid] += s_ej[tid] / (1.0f + s_nj);
        for (int idx = tid; idx < ND * ND; idx += 128)
            g_Smod[idx] = S_in[j * ND * ND + idx] + s_ej[idx >> 6] * s_ej[idx & 63];
        if (tid == 0) { g_n[j] = s_nj + 1.0f; g_modidx = j; s_c = j; }
    } else {
        const int ca = cact[0];
        if (tid < 64) g_mu[ca * ND + tid] = z[tid];
        for (int idx = tid; idx < ND * ND; idx += 128)
            g_Smod[idx] = ((idx >> 6) == (idx & 63)) ? 1.0f : 0.0f;
        if (tid == 0) { g_n[ca] = 1.0f; g_Gamma[ca] = 1.0f; g_active[ca] = 1;
                        g_modidx = ca; s_c = ca; }
    }
    __syncthreads();
    if (tid < NC)
        g_sel[tid] = (g_Gamma[tid] > 0.225f && g_active[tid]) ? 1 : 0;
    __syncthreads();
    // ---- k3_fix part: rebuild ZZ + Vii32 for cluster s_c from g_Smod ----
    const int c = s_c;
    const float nc   = g_n[c];
    const float coef = (nc - 1.0f) / nc;
    const float invn = 1.0f / nc;
    const float* mc = &g_mu[c * ND];
    const float4* Sc4 = reinterpret_cast<const float4*>(g_Smod);
    const float4* mc4 = reinterpret_cast<const float4*>(mc);
    float4* Z4 = reinterpret_cast<float4*>(&g_ZZ[c * ND * ND]);
    for (int t = tid; t < ND * ND / 4; t += 128) {
        float4 s = Sc4[t];
        float4 m = mc4[t & 15];
        float mr = mc[t >> 4];
        Z4[t] = make_float4(coef * s.x + mr * m.x, coef * s.y + mr * m.y,
                            coef * s.z + mr * m.z, coef * s.w + mr * m.w);
    }
    const int row = tid >> 1;
    const int c0  = (tid & 1) << 5;
    float a[32];
    const float4* Sr = reinterpret_cast<const float4*>(g_Smod + row * ND + c0);
#pragma unroll
    for (int q = 0; q < 8; ++q) {
        float4 v = Sr[q];
        a[4*q]   = v.x * invn;
        a[4*q+1] = v.y * invn;
        a[4*q+2] = v.z * invn;
        a[4*q+3] = v.w * invn;
    }
    __syncthreads();
    block_elim64f(a, s_piv, s_pk);
    double det = pivot_product(s_pk);
    if (tid == 0) g_Vii32[c] = (float)det;
}

// ---------------------------------------------------------------------------
// K4 (SCREEN, LDL^T): 64 threads/block. Thread t: r2 = t&31, h = t>>5
// (warp 0 = cols 0-31, warp 1 = cols 32-63 -> warp-uniform chunk predicates).
// Rows (r2, r2+32). Only the pivot COLUMN is broadcast (double-buffered
// s_col); multiplier f_r = col[r] * (1/d) — no shfl. Update is the outer
// product col x col on the lower triangle; upper-triangle register slots
// receive garbage that is provably never read.  det = prod d_k.
// launch_bounds(64, 10): cap regs at 102 so the RF holds 10 blocks/SM
// (was 8) — k4 concurrency is register-file-limited.
// ---------------------------------------------------------------------------
__global__ void __launch_bounds__(64, 10)
k4_pairs() {
    const int b = blockIdx.x;
    const int i = b >> 7;
    const int j = b & (NC - 1);
    const int tid = threadIdx.x;   // 64
    if (i >= j || !g_sel[i] || !g_sel[j]) {
        if (tid == 0) g_kappa[b] = f_inf();
        return;
    }
    __shared__ __align__(16) float s_col[2][64];
    __shared__ float s_pk[64];
    __shared__ float s_muij[64];
    const float ni = g_n[i], nj = g_n[j];
    const float nij = ni + nj;
    s_muij[tid] = (ni * g_mu[i * ND + tid] + nj * g_mu[j * ND + tid]) / nij;
    __syncthreads();
    const float invs = 1.0f / (nij - 1.0f);
    const int r2 = tid & 31;
    const int h  = tid >> 5;          // warp-uniform
    const int c0 = h << 5;
    const int rA = r2, rB = r2 + 32;
    float aA[32], aB[32];
    // row rB (always carries lower-triangle data in both halves)
    {
        const float mrB = s_muij[rB];
        const float4* zi4 = reinterpret_cast<const float4*>(&g_ZZ[i * ND * ND + rB * ND + c0]);
        const float4* zj4 = reinterpret_cast<const float4*>(&g_ZZ[j * ND * ND + rB * ND + c0]);
#pragma unroll
        for (int q = 0; q < 8; ++q) {
            float4 x = zi4[q], y = zj4[q];
            aB[4*q]   = (x.x + y.x - mrB * s_muij[c0 + 4*q])     * invs;
            aB[4*q+1] = (x.y + y.y - mrB * s_muij[c0 + 4*q + 1]) * invs;
            aB[4*q+2] = (x.z + y.z - mrB * s_muij[c0 + 4*q + 2]) * invs;
            aB[4*q+3] = (x.w + y.w - mrB * s_muij[c0 + 4*q + 3]) * invs;
        }
    }
    // row rA: lower part lives entirely in half 0 (rA <= 31)
    if (h == 0) {
        const float mrA = s_muij[rA];
        const float4* zi4 = reinterpret_cast<const float4*>(&g_ZZ[i * ND * ND + rA * ND]);
        const float4* zj4 = reinterpret_cast<const float4*>(&g_ZZ[j * ND * ND + rA * ND]);
#pragma unroll
        for (int q = 0; q < 8; ++q) {
            float4 x = zi4[q], y = zj4[q];
            aA[4*q]   = (x.x + y.x - mrA * s_muij[4*q])     * invs;
            aA[4*q+1] = (x.y + y.y - mrA * s_muij[4*q + 1]) * invs;
            aA[4*q+2] = (x.z + y.z - mrA * s_muij[4*q + 2]) * invs;
            aA[4*q+3] = (x.w + y.w - mrA * s_muij[4*q + 3]) * invs;
        }
        // initial publish: column 0 (elements (r,0) live in half 0)
        s_col[0][rA] = aA[0];
        s_col[0][rB] = aB[0];
    }
    __syncthreads();
#pragma unroll
    for (int k = 0; k < 64; ++k) {
        const float* cur = s_col[k & 1];
        const float d = cur[k];
        if (tid == 0) s_pk[k] = d;
        const float invd = __fdividef(1.0f, d);
        const float fA = cur[rA] * invd;
        const float fB = cur[rB] * invd;
        const bool uA = (h == 0) && (rA > k);
        const bool uB = (rB > k);
#pragma unroll
        for (int q = 0; q < 8; ++q) {
            if (c0 + 4*q + 3 > k) {        // warp-uniform live-chunk test
                float4 v = *reinterpret_cast<const float4*>(&cur[c0 + 4*q]);
                if (uA) {
                    aA[4*q]   -= fA * v.x;
                    aA[4*q+1] -= fA * v.y;
                    aA[4*q+2] -= fA * v.z;
                    aA[4*q+3] -= fA * v.w;
                }
                if (uB) {
                    aB[4*q]   -= fB * v.x;
                    aB[4*q+1] -= fB * v.y;
                    aB[4*q+2] -= fB * v.z;
                    aB[4*q+3] -= fB * v.w;
                }
            }
        }
        // publish column k+1 (post-update values) into the alternate buffer
        if (k < 63) {
            const int kk = k + 1;
            if ((kk >> 5) == h) {          // warp-uniform
                float* nxt = s_col[kk & 1];
                const int idx = kk & 31;   // static per unrolled k
                if (h == 0 && rA >= kk) nxt[rA] = aA[idx];
                if (rB >= kk)           nxt[rB] = aB[idx];
            }
        }
        __syncthreads();
    }
    double det = pivot_product(s_pk);
    if (tid == 0) {
        float kap = vij_valid(det) ? ((float)(det / (double)(g_Vii32[i] + g_Vii32[j])))
                                   : f_inf();
        g_kappa[b] = kap;
        if (kap < f_inf()) atomicMin(&g_kmin_key, f2key(kap));
    }
}

// ---------------------------------------------------------------------------
// K5a: parallel candidate collection near the global fp32 kmin.
// ---------------------------------------------------------------------------
__global__ void k5a_select() {
    const float kmin = key2f(g_kmin_key);
    if (!(kmin < 3.0e38f)) return;
    const float thr = kmin + (fabsf(kmin) * 1e-3f + 1e-30f);
    const int b = blockIdx.x * 256 + threadIdx.x;
    if (g_kappa[b] <= thr) {
        int p = atomicAdd(&g_ncand, 1);
        if (p < 128) g_cand[p] = b;
    }
}

// ---------------------------------------------------------------------------
// K5b0: fp64 Vii for clusters referenced by candidates (lazy; few blocks).
// ---------------------------------------------------------------------------
__global__ void k5b0_vii(const float* __restrict__ S_in) {
    const int ncand = min(g_ncand, 128);
    const int t = blockIdx.x;
    if (t >= 2 * ncand) return;
    const int flat = g_cand[t >> 1];
    const int c = (t & 1) ? (flat & (NC - 1)) : (flat >> 7);
    const int tid = threadIdx.x;
    __shared__ double s_piv[128];
    __shared__ double s_inv[2];
    const double invn = 1.0 / (double)g_n[c];
    const float* Sc = (c == g_modidx) ? g_Smod : (S_in + c * ND * ND);
    const int row = tid >> 1;
    const int c0  = (tid & 1) << 5;
    double a[32];
    const float* Sr = Sc + row * ND + c0;
#pragma unroll
    for (int q = 0; q < 32; ++q) a[q] = (double)Sr[q] * invn;
    double det = block_det64d(a, s_piv, s_inv);
    if (tid == 0) g_Vii64[c] = det;
}

// ---------------------------------------------------------------------------
// K5b: fp64 recompute of kappa for each candidate pair (same validity mask).
// ---------------------------------------------------------------------------
__global__ void k5b_refine() {
    const int b = blockIdx.x;
    const int ncand = min(g_ncand, 128);
    if (b >= ncand) return;
    const int tid = threadIdx.x;
    __shared__ double s_piv[128];
    __shared__ double s_inv[2];
    __shared__ double s_muij[64];
    const int flat = g_cand[b];
    const int i = flat >> 7;
    const int j = flat & (NC - 1);
    const double ni = (double)g_n[i], nj = (double)g_n[j];
    const double nij = ni + nj;
    if (tid < 64)
        s_muij[tid] = (ni * (double)g_mu[i * ND + tid] + nj * (double)g_mu[j * ND + tid]) / nij;
    __syncthreads();
    const double invs = 1.0 / (nij - 1.0);
    const int row = tid >> 1;
    const int c0  = (tid & 1) << 5;
    const double mr = s_muij[row];
    const float* zi = &g_ZZ[i * ND * ND + row * ND + c0];
    const float* zj = &g_ZZ[j * ND * ND + row * ND + c0];
    double a[32];
#pragma unroll
    for (int q = 0; q < 32; ++q)
        a[q] = ((double)zi[q] + (double)zj[q] - mr * s_muij[c0 + q]) * invs;
    double det = block_det64d(a, s_piv, s_inv);
    if (tid == 0)
        g_kval[b] = vij_valid(det) ? (det / (g_Vii64[i] + g_Vii64[j])) : d_inf();
}

// ---------------------------------------------------------------------------
// K5c: argmin over refined candidates (first-flat-index ties), conditional
// merge, write out = mu * active.
// ---------------------------------------------------------------------------
__global__ void k5c_final(float* __restrict__ out) {
    const int tid = threadIdx.x;   // 256
    __shared__ double s_val[256];
    __shared__ int    s_idx[256];
    const int ncand = min(g_ncand, 128);
    double bv = d_inf(); int bi = 0x7fffffff;
    for (int b = tid; b < ncand; b += 256) {
        double v = g_kval[b]; int fi = g_cand[b];
        if (v < bv || (v == bv && fi < bi)) { bv = v; bi = fi; }
    }
    s_val[tid] = bv; s_idx[tid] = bi;
    __syncthreads();
    for (int s = 128; s; s >>= 1) {
        if (tid < s) {
            double v2 = s_val[tid + s]; int i2 = s_idx[tid + s];
            if (v2 < s_val[tid] || (v2 == s_val[tid] && i2 < s_idx[tid])) {
                s_val[tid] = v2; s_idx[tid] = i2;
            }
        }
        __syncthreads();
    }
    __shared__ int s_mi, s_mj, s_do;
    __shared__ float s_nmi, s_nmj;
    if (tid == 0) {
        s_do = (s_val[0] < 0.9) ? 1 : 0;
        s_mi = s_idx[0] >> 7;
        s_mj = s_idx[0] & (NC - 1);
        if (s_do) { s_nmi = g_n[s_mi]; s_nmj = g_n[s_mj]; }
    }
    __syncthreads();
    if (s_do) {
        if (tid < 64) {
            const int mi = s_mi, mj = s_mj;
            g_mu[mi * ND + tid] =
                (s_nmi * g_mu[mi * ND + tid] + s_nmj * g_mu[mj * ND + tid]) / (s_nmi + s_nmj);
        }
        if (tid == 0) g_active[s_mj] = 0;
    }
    __syncthreads();
    for (int idx = tid; idx < NC * ND; idx += 256)
        out[idx] = g_active[idx >> 6] ? g_mu[idx] : 0.0f;
}

// ---------------------------------------------------------------------------
extern "C" void kernel_launch(void* const* d_in, const int* in_sizes, int n_in,
                              void* d_out, int out_size) {
    const float* z  = (const float*)d_in[0];
    const float* mu = (const float*)d_in[1];
    const float* S  = (const float*)d_in[2];
    const float* n  = (const float*)d_in[3];
    const int*   ca = (const int*)d_in[4];
    float* out = (float*)d_out;

    k1_gamma<<<NC, 128>>>(z, mu, S, n, ca);
    k23_update_fix<<<1, 128>>>(z, S, ca);
    k4_pairs<<<NC * NC, 64>>>();
    k5a_select<<<64, 256>>>();
    k5b0_vii<<<256, 128>>>(S);
    k5b_refine<<<128, 128>>>();
    k5c_final<<<1, 256>>>(out);
}

// round 11
// speedup vs baseline: 1.6117x; 1.0055x over previous
#include <cuda_runtime.h>
#include <math.h>

#define NC 128   // clusters
#define ND 64    // dimension
#define NPAIRS (NC * (NC - 1) / 2)   // 8128 upper-triangle pairs

// V_FACTOR = 2*pi^32/(64*31!) — reference multiplies det by this in fp32; the
// product underflows (FTZ -> 0) for tiny dets, which drives the validity mask.
#define V_FACTOR_D 3.080513e-20
#define FLT_MIN_NORMAL 1.1754943508222875e-38

// ---------------- device scratch (no allocations allowed) ----------------
static __device__ __align__(16) float g_mu[NC * ND];
static __device__ __align__(16) float g_Smod[ND * ND];   // the one mutated S row
static __device__ __align__(16) float g_ZZ[NC * ND * ND];
static __device__ float  g_n[NC];
static __device__ float  g_Gamma[NC];
static __device__ float  g_Vii32[NC];
static __device__ double g_Vii64[NC];
static __device__ float  g_kappa[NC * NC];
static __device__ int    g_active[NC];
static __device__ int    g_sel[NC];
static __device__ int    g_modidx;
static __device__ int    g_ncand;
static __device__ int    g_kmin_key;     // order-preserving int key of min kappa
static __device__ int    g_cand[128];
static __device__ double g_kval[128];

__device__ __forceinline__ float  f_inf() { return __int_as_float(0x7f800000); }
__device__ __forceinline__ double d_inf() { return __longlong_as_double(0x7ff0000000000000LL); }

__device__ __forceinline__ int f2key(float f) {
    int b = __float_as_int(f);
    return (b >= 0) ? b : (int)(~(unsigned)b);
}
__device__ __forceinline__ float key2f(int k) {
    return __int_as_float((k >= 0) ? k : (int)(~(unsigned)k));
}

// Emulate the reference's fp32 `V_ij = V_FACTOR*det > 0` test under FTZ.
__device__ __forceinline__ bool vij_valid(double det) {
    return (det > 0.0) && (det * V_FACTOR_D >= FLT_MIN_NORMAL);
}

// ---------------------------------------------------------------------------
// fp32 64x64 forward elimination (128-thread variant) — used by k1 / k3_fix.
// row = tid>>1, half = tid&1 owns cols [32*half, +32). 1 barrier/step via
// double-buffered pivot rows. Pivots stashed to s_pk for post-loop reduction.
// ---------------------------------------------------------------------------
__device__ __forceinline__ void block_elim64f(float a[32], float* s_piv, float* s_pk) {
    const int tid  = threadIdx.x;
    const int row  = tid >> 1;
    const int half = tid & 1;
    const int c0   = half << 5;
    if (row == 0) {
#pragma unroll
        for (int q = 0; q < 8; ++q)
            reinterpret_cast<float4*>(s_piv)[half * 8 + q] =
                make_float4(a[4*q], a[4*q+1], a[4*q+2], a[4*q+3]);
    }
    __syncthreads();
#pragma unroll
    for (int k = 0; k < 64; ++k) {
        const float* buf = s_piv + ((k & 1) << 6);
        float pk = buf[k];
        if (tid == 0) s_pk[k] = pk;
        float cand  = a[k & 31];
        float other = __shfl_xor_sync(0xffffffffu, cand, 1);
        float fr    = ((k >> 5) == half) ? cand : other;
        float f     = __fdividef(fr, pk);
        if (row > k) {
#pragma unroll
            for (int q = 0; q < 8; ++q) {
                if (c0 + 4*q + 3 >= k) {
                    float4 p = reinterpret_cast<const float4*>(buf)[half * 8 + q];
                    a[4*q]   -= f * p.x;
                    a[4*q+1] -= f * p.y;
                    a[4*q+2] -= f * p.z;
                    a[4*q+3] -= f * p.w;
                }
            }
        }
        if (row == k + 1) {
            float* nb = s_piv + (((k + 1) & 1) << 6);
#pragma unroll
            for (int q = 0; q < 8; ++q)
                reinterpret_cast<float4*>(nb)[half * 8 + q] =
                    make_float4(a[4*q], a[4*q+1], a[4*q+2], a[4*q+3]);
        }
        __syncthreads();
    }
}

// Warp-0 product of the 64 stashed pivots (result on thread 0).
__device__ __forceinline__ double pivot_product(const float* s_pk) {
    const int tid = threadIdx.x;
    double v = 1.0;
    if (tid < 32) {
        v = (double)s_pk[tid] * (double)s_pk[tid + 32];
#pragma unroll
        for (int off = 16; off; off >>= 1)
            v *= __shfl_down_sync(0xffffffffu, v, off);
    }
    return v;
}

// ---------------------------------------------------------------------------
// fp64 single-step engine — only candidate refinement (few blocks).
// ---------------------------------------------------------------------------
__device__ __forceinline__ double block_det64d(double a[32], double* s_piv, double* s_inv) {
    const int tid  = threadIdx.x;
    const int row  = tid >> 1;
    const int half = tid & 1;
    const int c0   = half << 5;
    if (row == 0) {
#pragma unroll
        for (int q = 0; q < 16; ++q)
            reinterpret_cast<double2*>(s_piv)[half * 16 + q] = make_double2(a[2*q], a[2*q+1]);
        if (tid == 0) s_inv[0] = 1.0 / a[0];
    }
    __syncthreads();
    double det = 1.0;
#pragma unroll
    for (int k = 0; k < 64; ++k) {
        const double* buf = s_piv + ((k & 1) << 6);
        double pk  = buf[k];
        double ipk = s_inv[k & 1];
        if (tid == 0) det *= pk;
        double cand  = a[k & 31];
        double other = __shfl_xor_sync(0xffffffffu, cand, 1);
        double fr    = ((k >> 5) == half) ? cand : other;
        double f     = fr * ipk;
        if (row > k) {
#pragma unroll
            for (int q = 0; q < 16; ++q) {
                if (c0 + 2*q + 1 >= k) {
                    double2 p = reinterpret_cast<const double2*>(buf)[half * 16 + q];
                    a[2*q]   -= f * p.x;
                    a[2*q+1] -= f * p.y;
                }
            }
        }
        if (row == k + 1) {
            double* nb = s_piv + (((k + 1) & 1) << 6);
#pragma unroll
            for (int q = 0; q < 16; ++q)
                reinterpret_cast<double2*>(nb)[half * 16 + q] = make_double2(a[2*q], a[2*q+1]);
            if (((k + 1) >> 5) == half) s_inv[(k + 1) & 1] = 1.0 / a[(k + 1) & 31];
        }
        __syncthreads();
    }
    return det;
}

// ---------------------------------------------------------------------------
// K1 (merged k0+k1+k3): init state (incl. g_kappa = inf), ZZ build, Vii32,
// Gamma.
// ---------------------------------------------------------------------------
__global__ void __launch_bounds__(128, 6)
k1_gamma(const float* __restrict__ z, const float* __restrict__ mu_in,
         const float* __restrict__ S_in, const float* __restrict__ n_in,
         const int* __restrict__ cact) {
    const int c = blockIdx.x;
    const int tid = threadIdx.x;
    __shared__ float s_piv[128];
    __shared__ float s_pk[64];
    __shared__ float s_x[64];
    __shared__ float s_e[64];
    const float nc = n_in[c];
    if (tid < 64) {
        float m = mu_in[c * ND + tid];
        g_mu[c * ND + tid] = m;
        float e = z[tid] - m;
        s_e[tid] = e;
        s_x[tid] = e;
    }
    // g_kappa row init: cells not written by the triangular k4 must be +inf
    g_kappa[c * NC + tid] = f_inf();
    if (tid == 0) {
        g_n[c] = nc;
        g_active[c] = (c < cact[0]) ? 1 : 0;
        if (c == 0) { g_kmin_key = 0x7f800000; g_ncand = 0; }
    }
    // ZZ build from INPUT S, mu (k3_fix patches the one mutated cluster)
    {
        const float coef = (nc - 1.0f) / nc;
        const float* mc = mu_in + c * ND;
        const float4* Sc4 = reinterpret_cast<const float4*>(S_in + c * ND * ND);
        const float4* mc4 = reinterpret_cast<const float4*>(mc);
        float4* Z4 = reinterpret_cast<float4*>(&g_ZZ[c * ND * ND]);
        for (int t = tid; t < ND * ND / 4; t += 128) {
            float4 s = Sc4[t];
            float4 m = mc4[t & 15];
            float mr = mc[t >> 4];
            Z4[t] = make_float4(coef * s.x + mr * m.x, coef * s.y + mr * m.y,
                                coef * s.z + mr * m.z, coef * s.w + mr * m.w);
        }
    }
    // elimination on S/n with RHS solve
    const float invn = 1.0f / nc;
    const int row  = tid >> 1;
    const int half = tid & 1;
    const int c0   = half << 5;
    float a[32];
    {
        const float4* Sr = reinterpret_cast<const float4*>(S_in + c * ND * ND + row * ND + c0);
#pragma unroll
        for (int q = 0; q < 8; ++q) {
            float4 v = Sr[q];
            a[4*q]   = v.x * invn;
            a[4*q+1] = v.y * invn;
            a[4*q+2] = v.z * invn;
            a[4*q+3] = v.w * invn;
        }
    }
    if (row == 0) {
#pragma unroll
        for (int q = 0; q < 8; ++q)
            reinterpret_cast<float4*>(s_piv)[half * 8 + q] =
                make_float4(a[4*q], a[4*q+1], a[4*q+2], a[4*q+3]);
    }
    __syncthreads();
#pragma unroll
    for (int k = 0; k < 64; ++k) {
        const float* buf = s_piv + ((k & 1) << 6);
        float pk = buf[k];
        float xk = s_x[k];
        if (tid == 0) s_pk[k] = pk;
        float cand  = a[k & 31];
        float other = __shfl_xor_sync(0xffffffffu, cand, 1);
        float fr    = ((k >> 5) == half) ? cand : other;
        float f     = __fdividef(fr, pk);
        if (row > k) {
#pragma unroll
            for (int q = 0; q < 8; ++q) {
                if (c0 + 4*q + 3 >= k) {
                    float4 p = reinterpret_cast<const float4*>(buf)[half * 8 + q];
                    a[4*q]   -= f * p.x;
                    a[4*q+1] -= f * p.y;
                    a[4*q+2] -= f * p.z;
                    a[4*q+3] -= f * p.w;
                }
            }
            if (half == 0) s_x[row] -= f * xk;   // one writer per row
        }
        if (row == k + 1) {
            float* nb = s_piv + (((k + 1) & 1) << 6);
#pragma unroll
            for (int q = 0; q < 8; ++q)
                reinterpret_cast<float4*>(nb)[half * 8 + q] =
                    make_float4(a[4*q], a[4*q+1], a[4*q+2], a[4*q+3]);
        }
        __syncthreads();
    }
    // post-loop reductions (warp 0): d2_euc, d2_mah, det
    if (tid < 32) {
        float e0 = s_e[tid], e1 = s_e[tid + 32];
        float x0 = s_x[tid], x1 = s_x[tid + 32];
        float p0 = s_pk[tid], p1 = s_pk[tid + 32];
        float deuc = e0 * e0 + e1 * e1;
        double dmah = (double)(x0 * x0) / (double)p0 + (double)(x1 * x1) / (double)p1;
        double dprod = (double)p0 * (double)p1;
#pragma unroll
        for (int off = 16; off; off >>= 1) {
            deuc  += __shfl_down_sync(0xffffffffu, deuc, off);
            dmah  += __shfl_down_sync(0xffffffffu, dmah, off);
            dprod *= __shfl_down_sync(0xffffffffu, dprod, off);
        }
        if (tid == 0) {
            float d2 = (nc < 100.0f) ? deuc : (float)dmah;
            g_Gamma[c] = (c < cact[0]) ? expf(-d2) : 0.0f;
            g_Vii32[c] = (float)dprod;
        }
    }
}

// ---------------------------------------------------------------------------
// K2: warp-parallel argmax Gamma (first-index ties), incremental update or
// spawn (S mutation stored as g_Smod + g_modidx), then sel.
// ---------------------------------------------------------------------------
__global__ void k2_update(const float* __restrict__ z, const float* __restrict__ S_in,
                          const int* __restrict__ cact) {
    const int tid = threadIdx.x;   // 256
    __shared__ float s_ej[64];
    __shared__ int s_j, s_incr;
    __shared__ float s_nj;
    if (tid < 32) {
        float bv = g_Gamma[tid]; int bi = tid;
#pragma unroll
        for (int t = 1; t < 4; ++t) {
            float v = g_Gamma[tid + 32 * t];
            if (v > bv) { bv = v; bi = tid + 32 * t; }   // increasing idx: strict >
        }
#pragma unroll
        for (int off = 16; off; off >>= 1) {
            float ov = __shfl_down_sync(0xffffffffu, bv, off);
            int   oi = __shfl_down_sync(0xffffffffu, bi, off);
            if (ov > bv || (ov == bv && oi < bi)) { bv = ov; bi = oi; }
        }
        if (tid == 0) {
            s_j = bi;
            s_incr = (bv > 0.9f) ? 1 : 0;
            s_nj = g_n[bi];
        }
    }
    __syncthreads();
    if (s_incr) {
        const int j = s_j;
        if (tid < 64) s_ej[tid] = z[tid] - g_mu[j * ND + tid];
        __syncthreads();
        if (tid < 64) g_mu[j * ND + tid] += s_ej[tid] / (1.0f + s_nj);
        for (int idx = tid; idx < ND * ND; idx += 256)
            g_Smod[idx] = S_in[j * ND * ND + idx] + s_ej[idx >> 6] * s_ej[idx & 63];
        if (tid == 0) { g_n[j] = s_nj + 1.0f; g_modidx = j; }
    } else {
        const int ca = cact[0];
        if (tid < 64) g_mu[ca * ND + tid] = z[tid];
        for (int idx = tid; idx < ND * ND; idx += 256)
            g_Smod[idx] = ((idx >> 6) == (idx & 63)) ? 1.0f : 0.0f;
        if (tid == 0) { g_n[ca] = 1.0f; g_Gamma[ca] = 1.0f; g_active[ca] = 1; g_modidx = ca; }
    }
    __syncthreads();
    if (tid < NC)
        g_sel[tid] = (g_Gamma[tid] > 0.225f && g_active[tid]) ? 1 : 0;
}

// ---------------------------------------------------------------------------
// K3fix (1 block): rebuild ZZ and Vii32 for the single mutated cluster.
// ---------------------------------------------------------------------------
__global__ void __launch_bounds__(128, 6)
k3_fix() {
    const int c = g_modidx;
    const int tid = threadIdx.x;
    __shared__ float s_piv[128];
    __shared__ float s_pk[64];
    const float nc   = g_n[c];
    const float coef = (nc - 1.0f) / nc;
    const float invn = 1.0f / nc;
    const float* mc = &g_mu[c * ND];
    const float4* Sc4 = reinterpret_cast<const float4*>(g_Smod);
    const float4* mc4 = reinterpret_cast<const float4*>(mc);
    float4* Z4 = reinterpret_cast<float4*>(&g_ZZ[c * ND * ND]);
    for (int t = tid; t < ND * ND / 4; t += 128) {
        float4 s = Sc4[t];
        float4 m = mc4[t & 15];
        float mr = mc[t >> 4];
        Z4[t] = make_float4(coef * s.x + mr * m.x, coef * s.y + mr * m.y,
                            coef * s.z + mr * m.z, coef * s.w + mr * m.w);
    }
    const int row = tid >> 1;
    const int c0  = (tid & 1) << 5;
    float a[32];
    const float4* Sr = reinterpret_cast<const float4*>(g_Smod + row * ND + c0);
#pragma unroll
    for (int q = 0; q < 8; ++q) {
        float4 v = Sr[q];
        a[4*q]   = v.x * invn;
        a[4*q+1] = v.y * invn;
        a[4*q+2] = v.z * invn;
        a[4*q+3] = v.w * invn;
    }
    __syncthreads();
    block_elim64f(a, s_piv, s_pk);
    double det = pivot_product(s_pk);
    if (tid == 0) g_Vii32[c] = (float)det;
}

// ---------------------------------------------------------------------------
// K4 (SCREEN, LDL^T): triangular grid — exactly NPAIRS blocks, (i,j) decoded
// from the triangular index (no dead i>=j CTAs). 64 threads/block. Thread t:
// r2 = t&31, h = t>>5 (warp 0 = cols 0-31, warp 1 = cols 32-63 ->
// warp-uniform chunk predicates). Rows (r2, r2+32). Only the pivot COLUMN is
// broadcast (double-buffered s_col); multiplier f_r = col[r]*(1/d) — no shfl.
// Outer-product update on the lower triangle; upper-triangle register slots
// receive garbage that is provably never read.  det = prod d_k.
// ---------------------------------------------------------------------------
__global__ void __launch_bounds__(64, 10)
k4_pairs() {
    const int b = blockIdx.x;          // 0 .. NPAIRS-1
    // triangular decode: i = largest r with base(r) <= b, base(r)=r*(2*NC-r-1)/2
    int i = (int)((float)NC - 0.5f
                  - sqrtf(((float)NC - 0.5f) * ((float)NC - 0.5f) - 2.0f * (float)b));
    if (i < 0) i = 0;
    if (i > NC - 2) i = NC - 2;
    while (i > 0 && (i * (2 * NC - i - 1)) / 2 > b) --i;
    while (((i + 1) * (2 * NC - i - 2)) / 2 <= b) ++i;
    const int j = b - (i * (2 * NC - i - 1)) / 2 + i + 1;
    const int tid = threadIdx.x;   // 64
    if (!g_sel[i] || !g_sel[j]) return;     // g_kappa pre-initialized to inf
    __shared__ __align__(16) float s_col[2][64];
    __shared__ float s_pk[64];
    __shared__ float s_muij[64];
    const float ni = g_n[i], nj = g_n[j];
    const float nij = ni + nj;
    s_muij[tid] = (ni * g_mu[i * ND + tid] + nj * g_mu[j * ND + tid]) / nij;
    __syncthreads();
    const float invs = 1.0f / (nij - 1.0f);
    const int r2 = tid & 31;
    const int h  = tid >> 5;          // warp-uniform
    const int c0 = h << 5;
    const int rA = r2, rB = r2 + 32;
    float aA[32], aB[32];
    // row rB (always carries lower-triangle data in both halves)
    {
        const float mrB = s_muij[rB];
        const float4* zi4 = reinterpret_cast<const float4*>(&g_ZZ[i * ND * ND + rB * ND + c0]);
        const float4* zj4 = reinterpret_cast<const float4*>(&g_ZZ[j * ND * ND + rB * ND + c0]);
#pragma unroll
        for (int q = 0; q < 8; ++q) {
            float4 x = zi4[q], y = zj4[q];
            aB[4*q]   = (x.x + y.x - mrB * s_muij[c0 + 4*q])     * invs;
            aB[4*q+1] = (x.y + y.y - mrB * s_muij[c0 + 4*q + 1]) * invs;
            aB[4*q+2] = (x.z + y.z - mrB * s_muij[c0 + 4*q + 2]) * invs;
            aB[4*q+3] = (x.w + y.w - mrB * s_muij[c0 + 4*q + 3]) * invs;
        }
    }
    // row rA: lower part lives entirely in half 0 (rA <= 31)
    if (h == 0) {
        const float mrA = s_muij[rA];
        const float4* zi4 = reinterpret_cast<const float4*>(&g_ZZ[i * ND * ND + rA * ND]);
        const float4* zj4 = reinterpret_cast<const float4*>(&g_ZZ[j * ND * ND + rA * ND]);
#pragma unroll
        for (int q = 0; q < 8; ++q) {
            float4 x = zi4[q], y = zj4[q];
            aA[4*q]   = (x.x + y.x - mrA * s_muij[4*q])     * invs;
            aA[4*q+1] = (x.y + y.y - mrA * s_muij[4*q + 1]) * invs;
            aA[4*q+2] = (x.z + y.z - mrA * s_muij[4*q + 2]) * invs;
            aA[4*q+3] = (x.w + y.w - mrA * s_muij[4*q + 3]) * invs;
        }
        // initial publish: column 0 (elements (r,0) live in half 0)
        s_col[0][rA] = aA[0];
        s_col[0][rB] = aB[0];
    }
    __syncthreads();
#pragma unroll
    for (int k = 0; k < 64; ++k) {
        const float* cur = s_col[k & 1];
        const float d = cur[k];
        if (tid == 0) s_pk[k] = d;
        const float invd = __fdividef(1.0f, d);
        const float fA = cur[rA] * invd;
        const float fB = cur[rB] * invd;
        const bool uA = (h == 0) && (rA > k);
        const bool uB = (rB > k);
#pragma unroll
        for (int q = 0; q < 8; ++q) {
            if (c0 + 4*q + 3 > k) {        // warp-uniform live-chunk test
                float4 v = *reinterpret_cast<const float4*>(&cur[c0 + 4*q]);
                if (uA) {
                    aA[4*q]   -= fA * v.x;
                    aA[4*q+1] -= fA * v.y;
                    aA[4*q+2] -= fA * v.z;
                    aA[4*q+3] -= fA * v.w;
                }
                if (uB) {
                    aB[4*q]   -= fB * v.x;
                    aB[4*q+1] -= fB * v.y;
                    aB[4*q+2] -= fB * v.z;
                    aB[4*q+3] -= fB * v.w;
                }
            }
        }
        // publish column k+1 (post-update values) into the alternate buffer
        if (k < 63) {
            const int kk = k + 1;
            if ((kk >> 5) == h) {          // warp-uniform
                float* nxt = s_col[kk & 1];
                const int idx = kk & 31;   // static per unrolled k
                if (h == 0 && rA >= kk) nxt[rA] = aA[idx];
                if (rB >= kk)           nxt[rB] = aB[idx];
            }
        }
        __syncthreads();
    }
    double det = pivot_product(s_pk);
    if (tid == 0) {
        float kap = vij_valid(det) ? ((float)(det / (double)(g_Vii32[i] + g_Vii32[j])))
                                   : f_inf();
        g_kappa[i * NC + j] = kap;
        if (kap < f_inf()) atomicMin(&g_kmin_key, f2key(kap));
    }
}

// ---------------------------------------------------------------------------
// K5a: parallel candidate collection near the global fp32 kmin.
// ---------------------------------------------------------------------------
__global__ void k5a_select() {
    const float kmin = key2f(g_kmin_key);
    if (!(kmin < 3.0e38f)) return;
    const float thr = kmin + (fabsf(kmin) * 1e-3f + 1e-30f);
    const int b = blockIdx.x * 256 + threadIdx.x;
    if (g_kappa[b] <= thr) {
        int p = atomicAdd(&g_ncand, 1);
        if (p < 128) g_cand[p] = b;
    }
}

// ---------------------------------------------------------------------------
// K5b0: fp64 Vii for clusters referenced by candidates (lazy; few blocks).
// ---------------------------------------------------------------------------
__global__ void k5b0_vii(const float* __restrict__ S_in) {
    const int ncand = min(g_ncand, 128);
    const int t = blockIdx.x;
    if (t >= 2 * ncand) return;
    const int flat = g_cand[t >> 1];
    const int c = (t & 1) ? (flat & (NC - 1)) : (flat >> 7);
    const int tid = threadIdx.x;
    __shared__ double s_piv[128];
    __shared__ double s_inv[2];
    const double invn = 1.0 / (double)g_n[c];
    const float* Sc = (c == g_modidx) ? g_Smod : (S_in + c * ND * ND);
    const int row = tid >> 1;
    const int c0  = (tid & 1) << 5;
    double a[32];
    const float* Sr = Sc + row * ND + c0;
#pragma unroll
    for (int q = 0; q < 32; ++q) a[q] = (double)Sr[q] * invn;
    double det = block_det64d(a, s_piv, s_inv);
    if (tid == 0) g_Vii64[c] = det;
}

// ---------------------------------------------------------------------------
// K5b: fp64 recompute of kappa for each candidate pair (same validity mask).
// ---------------------------------------------------------------------------
__global__ void k5b_refine() {
    const int b = blockIdx.x;
    const int ncand = min(g_ncand, 128);
    if (b >= ncand) return;
    const int tid = threadIdx.x;
    __shared__ double s_piv[128];
    __shared__ double s_inv[2];
    __shared__ double s_muij[64];
    const int flat = g_cand[b];
    const int i = flat >> 7;
    const int j = flat & (NC - 1);
    const double ni = (double)g_n[i], nj = (double)g_n[j];
    const double nij = ni + nj;
    if (tid < 64)
        s_muij[tid] = (ni * (double)g_mu[i * ND + tid] + nj * (double)g_mu[j * ND + tid]) / nij;
    __syncthreads();
    const double invs = 1.0 / (nij - 1.0);
    const int row = tid >> 1;
    const int c0  = (tid & 1) << 5;
    const double mr = s_muij[row];
    const float* zi = &g_ZZ[i * ND * ND + row * ND + c0];
    const float* zj = &g_ZZ[j * ND * ND + row * ND + c0];
    double a[32];
#pragma unroll
    for (int q = 0; q < 32; ++q)
        a[q] = ((double)zi[q] + (double)zj[q] - mr * s_muij[c0 + q]) * invs;
    double det = block_det64d(a, s_piv, s_inv);
    if (tid == 0)
        g_kval[b] = vij_valid(det) ? (det / (g_Vii64[i] + g_Vii64[j])) : d_inf();
}

// ---------------------------------------------------------------------------
// K5c: argmin over refined candidates (first-flat-index ties), conditional
// merge, write out = mu * active.
// ---------------------------------------------------------------------------
__global__ void k5c_final(float* __restrict__ out) {
    const int tid = threadIdx.x;   // 256
    __shared__ double s_val[256];
    __shared__ int    s_idx[256];
    const int ncand = min(g_ncand, 128);
    double bv = d_inf(); int bi = 0x7fffffff;
    for (int b = tid; b < ncand; b += 256) {
        double v = g_kval[b]; int fi = g_cand[b];
        if (v < bv || (v == bv && fi < bi)) { bv = v; bi = fi; }
    }
    s_val[tid] = bv; s_idx[tid] = bi;
    __syncthreads();
    for (int s = 128; s; s >>= 1) {
        if (tid < s) {
            double v2 = s_val[tid + s]; int i2 = s_idx[tid + s];
            if (v2 < s_val[tid] || (v2 == s_val[tid] && i2 < s_idx[tid])) {
                s_val[tid] = v2; s_idx[tid] = i2;
            }
        }
        __syncthreads();
    }
    __shared__ int s_mi, s_mj, s_do;
    __shared__ float s_nmi, s_nmj;
    if (tid == 0) {
        s_do = (s_val[0] < 0.9) ? 1 : 0;
        s_mi = s_idx[0] >> 7;
        s_mj = s_idx[0] & (NC - 1);
        if (s_do) { s_nmi = g_n[s_mi]; s_nmj = g_n[s_mj]; }
    }
    __syncthreads();
    if (s_do) {
        if (tid < 64) {
            const int mi = s_mi, mj = s_mj;
            g_mu[mi * ND + tid] =
                (s_nmi * g_mu[mi * ND + tid] + s_nmj * g_mu[mj * ND + tid]) / (s_nmi + s_nmj);
        }
        if (tid == 0) g_active[s_mj] = 0;
    }
    __syncthreads();
    for (int idx = tid; idx < NC * ND; idx += 256)
        out[idx] = g_active[idx >> 6] ? g_mu[idx] : 0.0f;
}

// ---------------------------------------------------------------------------
extern "C" void kernel_launch(void* const* d_in, const int* in_sizes, int n_in,
                              void* d_out, int out_size) {
    const float* z  = (const float*)d_in[0];
    const float* mu = (const float*)d_in[1];
    const float* S  = (const float*)d_in[2];
    const float* n  = (const float*)d_in[3];
    const int*   ca = (const int*)d_in[4];
    float* out = (float*)d_out;

    k1_gamma<<<NC, 128>>>(z, mu, S, n, ca);
    k2_update<<<1, 256>>>(z, S, ca);
    k3_fix<<<1, 128>>>();
    k4_pairs<<<NPAIRS, 64>>>();           // 4th launch -> ncu capture slot
    k5a_select<<<64, 256>>>();
    k5b0_vii<<<256, 128>>>(S);
    k5b_refine<<<128, 128>>>();
    k5c_final<<<1, 256>>>(out);
}

// round 12
// speedup vs baseline: 1.8049x; 1.1198x over previous
#include <cuda_runtime.h>
#include <math.h>

#define NC 128   // clusters
#define ND 64    // dimension
#define NPAIRS (NC * (NC - 1) / 2)   // 8128 upper-triangle pairs

// V_FACTOR = 2*pi^32/(64*31!) — reference multiplies det by this in fp32; the
// product underflows (FTZ -> 0) for tiny dets, which drives the validity mask.
#define V_FACTOR_D 3.080513e-20
#define FLT_MIN_NORMAL 1.1754943508222875e-38

// ---------------- device scratch (no allocations allowed) ----------------
static __device__ __align__(16) float g_mu[NC * ND];
static __device__ __align__(16) float g_Smod[ND * ND];   // the one mutated S row
static __device__ __align__(16) float g_ZZ[NC * ND * ND];
static __device__ float  g_n[NC];
static __device__ float  g_Gamma[NC];
static __device__ float  g_Vii32[NC];
static __device__ float  g_kappa[NC * NC];
static __device__ int    g_active[NC];
static __device__ int    g_sel[NC];
static __device__ int    g_modidx;
static __device__ int    g_ncand;
static __device__ int    g_kmin_key;     // order-preserving int key of min kappa
static __device__ int    g_cand[128];
static __device__ double g_kval[128];

__device__ __forceinline__ float  f_inf() { return __int_as_float(0x7f800000); }
__device__ __forceinline__ double d_inf() { return __longlong_as_double(0x7ff0000000000000LL); }

__device__ __forceinline__ int f2key(float f) {
    int b = __float_as_int(f);
    return (b >= 0) ? b : (int)(~(unsigned)b);
}
__device__ __forceinline__ float key2f(int k) {
    return __int_as_float((k >= 0) ? k : (int)(~(unsigned)k));
}

// Emulate the reference's fp32 `V_ij = V_FACTOR*det > 0` test under FTZ.
__device__ __forceinline__ bool vij_valid(double det) {
    return (det > 0.0) && (det * V_FACTOR_D >= FLT_MIN_NORMAL);
}

// ---------------------------------------------------------------------------
// fp32 64x64 forward elimination (128-thread row engine) — used by k3_fix.
// ---------------------------------------------------------------------------
__device__ __forceinline__ void block_elim64f(float a[32], float* s_piv, float* s_pk) {
    const int tid  = threadIdx.x;
    const int row  = tid >> 1;
    const int half = tid & 1;
    const int c0   = half << 5;
    if (row == 0) {
#pragma unroll
        for (int q = 0; q < 8; ++q)
            reinterpret_cast<float4*>(s_piv)[half * 8 + q] =
                make_float4(a[4*q], a[4*q+1], a[4*q+2], a[4*q+3]);
    }
    __syncthreads();
#pragma unroll
    for (int k = 0; k < 64; ++k) {
        const float* buf = s_piv + ((k & 1) << 6);
        float pk = buf[k];
        if (tid == 0) s_pk[k] = pk;
        float cand  = a[k & 31];
        float other = __shfl_xor_sync(0xffffffffu, cand, 1);
        float fr    = ((k >> 5) == half) ? cand : other;
        float f     = __fdividef(fr, pk);
        if (row > k) {
#pragma unroll
            for (int q = 0; q < 8; ++q) {
                if (c0 + 4*q + 3 >= k) {
                    float4 p = reinterpret_cast<const float4*>(buf)[half * 8 + q];
                    a[4*q]   -= f * p.x;
                    a[4*q+1] -= f * p.y;
                    a[4*q+2] -= f * p.z;
                    a[4*q+3] -= f * p.w;
                }
            }
        }
        if (row == k + 1) {
            float* nb = s_piv + (((k + 1) & 1) << 6);
#pragma unroll
            for (int q = 0; q < 8; ++q)
                reinterpret_cast<float4*>(nb)[half * 8 + q] =
                    make_float4(a[4*q], a[4*q+1], a[4*q+2], a[4*q+3]);
        }
        __syncthreads();
    }
}

// Warp-0 product of the 64 stashed pivots (result on thread 0).
__device__ __forceinline__ double pivot_product(const float* s_pk) {
    const int tid = threadIdx.x;
    double v = 1.0;
    if (tid < 32) {
        v = (double)s_pk[tid] * (double)s_pk[tid + 32];
#pragma unroll
        for (int off = 16; off; off >>= 1)
            v *= __shfl_down_sync(0xffffffffu, v, off);
    }
    return v;
}

// ---------------------------------------------------------------------------
// fp64 single-step engine — only candidate refinement (few blocks).
// ---------------------------------------------------------------------------
__device__ __forceinline__ double block_det64d(double a[32], double* s_piv, double* s_inv) {
    const int tid  = threadIdx.x;
    const int row  = tid >> 1;
    const int half = tid & 1;
    const int c0   = half << 5;
    if (row == 0) {
#pragma unroll
        for (int q = 0; q < 16; ++q)
            reinterpret_cast<double2*>(s_piv)[half * 16 + q] = make_double2(a[2*q], a[2*q+1]);
        if (tid == 0) s_inv[0] = 1.0 / a[0];
    }
    __syncthreads();
    double det = 1.0;
#pragma unroll
    for (int k = 0; k < 64; ++k) {
        const double* buf = s_piv + ((k & 1) << 6);
        double pk  = buf[k];
        double ipk = s_inv[k & 1];
        if (tid == 0) det *= pk;
        double cand  = a[k & 31];
        double other = __shfl_xor_sync(0xffffffffu, cand, 1);
        double fr    = ((k >> 5) == half) ? cand : other;
        double f     = fr * ipk;
        if (row > k) {
#pragma unroll
            for (int q = 0; q < 16; ++q) {
                if (c0 + 2*q + 1 >= k) {
                    double2 p = reinterpret_cast<const double2*>(buf)[half * 16 + q];
                    a[2*q]   -= f * p.x;
                    a[2*q+1] -= f * p.y;
                }
            }
        }
        if (row == k + 1) {
            double* nb = s_piv + (((k + 1) & 1) << 6);
#pragma unroll
            for (int q = 0; q < 16; ++q)
                reinterpret_cast<double2*>(nb)[half * 16 + q] = make_double2(a[2*q], a[2*q+1]);
            if (((k + 1) >> 5) == half) s_inv[(k + 1) & 1] = 1.0 / a[(k + 1) & 31];
        }
        __syncthreads();
    }
    return det;
}

// ---------------------------------------------------------------------------
// K1 (column-LDL^T engine, 64 threads): per cluster c —
//  - copy mu / n / active into working state; init g_kappa row to +inf
//  - ZZ_c = ((n-1)/n) S + mu mu^T
//  - LDL^T of S/n with folded RHS solve (x in warp-0 registers):
//    Vii32 = prod d_k; d2_mah = sum x_k^2/d_k; d2_euc from e pre-loop.
//  - Gamma = active ? exp(-d2) : 0
// ---------------------------------------------------------------------------
__global__ void __launch_bounds__(64, 10)
k1_gamma(const float* __restrict__ z, const float* __restrict__ mu_in,
         const float* __restrict__ S_in, const float* __restrict__ n_in,
         const int* __restrict__ cact) {
    const int c = blockIdx.x;
    const int tid = threadIdx.x;   // 64
    __shared__ __align__(16) float s_col[2][64];
    __shared__ float s_pk[64];
    __shared__ float s_xk[64];
    const float nc = n_in[c];
    const int lane = tid & 31;
    const int h    = tid >> 5;      // warp-uniform
    const int c0   = h << 5;
    const int rA = lane, rB = lane + 32;
    // state copy + kappa row init
    {
        float m = mu_in[c * ND + tid];
        g_mu[c * ND + tid] = m;
    }
    g_kappa[c * NC + tid]      = f_inf();
    g_kappa[c * NC + tid + 64] = f_inf();
    if (tid == 0) {
        g_n[c] = nc;
        g_active[c] = (c < cact[0]) ? 1 : 0;
        if (c == 0) { g_kmin_key = 0x7f800000; g_ncand = 0; }
    }
    // ZZ build from INPUT S, mu
    {
        const float coef = (nc - 1.0f) / nc;
        const float* mc = mu_in + c * ND;
        const float4* Sc4 = reinterpret_cast<const float4*>(S_in + c * ND * ND);
        const float4* mc4 = reinterpret_cast<const float4*>(mc);
        float4* Z4 = reinterpret_cast<float4*>(&g_ZZ[c * ND * ND]);
        for (int t = tid; t < ND * ND / 4; t += 64) {
            float4 s = Sc4[t];
            float4 m = mc4[t & 15];
            float mr = mc[t >> 4];
            Z4[t] = make_float4(coef * s.x + mr * m.x, coef * s.y + mr * m.y,
                                coef * s.z + mr * m.z, coef * s.w + mr * m.w);
        }
    }
    // matrix rows (S/n) for this thread
    const float invn = 1.0f / nc;
    float aA[32], aB[32];
    {
        const float4* SB = reinterpret_cast<const float4*>(S_in + c * ND * ND + rB * ND + c0);
#pragma unroll
        for (int q = 0; q < 8; ++q) {
            float4 v = SB[q];
            aB[4*q]   = v.x * invn;
            aB[4*q+1] = v.y * invn;
            aB[4*q+2] = v.z * invn;
            aB[4*q+3] = v.w * invn;
        }
    }
    float xA = 0.0f, xB = 0.0f;
    float deuc = 0.0f;   // valid on warp-0 lane 0 after reduction
    if (h == 0) {
        const float4* SA = reinterpret_cast<const float4*>(S_in + c * ND * ND + rA * ND);
#pragma unroll
        for (int q = 0; q < 8; ++q) {
            float4 v = SA[q];
            aA[4*q]   = v.x * invn;
            aA[4*q+1] = v.y * invn;
            aA[4*q+2] = v.z * invn;
            aA[4*q+3] = v.w * invn;
        }
        xA = z[rA] - mu_in[c * ND + rA];
        xB = z[rB] - mu_in[c * ND + rB];
        deuc = xA * xA + xB * xB;
#pragma unroll
        for (int off = 16; off; off >>= 1)
            deuc += __shfl_down_sync(0xffffffffu, deuc, off);
        // initial publish: column 0 + x[0]
        s_col[0][rA] = aA[0];
        s_col[0][rB] = aB[0];
        if (rA == 0) s_xk[0] = xA;
    }
    __syncthreads();
#pragma unroll
    for (int k = 0; k < 64; ++k) {
        const float* cur = s_col[k & 1];
        const float d = cur[k];
        if (tid == 0) s_pk[k] = d;
        const float invd = __fdividef(1.0f, d);
        const float fA = cur[rA] * invd;
        const float fB = cur[rB] * invd;
        const float xk = s_xk[k];
        const bool uA = (h == 0) && (rA > k);
        const bool uB = (rB > k);
#pragma unroll
        for (int q = 0; q < 8; ++q) {
            if (c0 + 4*q + 3 > k) {        // warp-uniform live-chunk test
                float4 v = *reinterpret_cast<const float4*>(&cur[c0 + 4*q]);
                if (uA) {
                    aA[4*q]   -= fA * v.x;
                    aA[4*q+1] -= fA * v.y;
                    aA[4*q+2] -= fA * v.z;
                    aA[4*q+3] -= fA * v.w;
                }
                if (uB) {
                    aB[4*q]   -= fB * v.x;
                    aB[4*q+1] -= fB * v.y;
                    aB[4*q+2] -= fB * v.z;
                    aB[4*q+3] -= fB * v.w;
                }
            }
        }
        if (h == 0) {
            if (rA > k) xA -= fA * xk;
            if (rB > k) xB -= fB * xk;
        }
        if (k < 63) {
            const int kk = k + 1;
            if ((kk >> 5) == h) {          // warp-uniform column publish
                float* nxt = s_col[kk & 1];
                const int idx = kk & 31;
                if (h == 0 && rA >= kk) nxt[rA] = aA[idx];
                if (rB >= kk)           nxt[rB] = aB[idx];
            }
            if (h == 0 && rA == (kk & 31))   // x publish (warp 0 owns x)
                s_xk[kk] = (kk < 32) ? xA : xB;
        }
        __syncthreads();
    }
    // post-loop reductions (warp 0): d2_mah, det
    if (tid < 32) {
        float x0 = s_xk[tid], x1 = s_xk[tid + 32];
        float p0 = s_pk[tid], p1 = s_pk[tid + 32];
        double dmah = (double)(x0 * x0) / (double)p0 + (double)(x1 * x1) / (double)p1;
        double dprod = (double)p0 * (double)p1;
#pragma unroll
        for (int off = 16; off; off >>= 1) {
            dmah  += __shfl_down_sync(0xffffffffu, dmah, off);
            dprod *= __shfl_down_sync(0xffffffffu, dprod, off);
        }
        if (tid == 0) {
            float d2 = (nc < 100.0f) ? deuc : (float)dmah;
            g_Gamma[c] = (c < cact[0]) ? expf(-d2) : 0.0f;
            g_Vii32[c] = (float)dprod;
        }
    }
}

// ---------------------------------------------------------------------------
// K2: warp-parallel argmax Gamma (first-index ties), incremental update or
// spawn (S mutation stored as g_Smod + g_modidx), then sel.
// ---------------------------------------------------------------------------
__global__ void k2_update(const float* __restrict__ z, const float* __restrict__ S_in,
                          const int* __restrict__ cact) {
    const int tid = threadIdx.x;   // 256
    __shared__ float s_ej[64];
    __shared__ int s_j, s_incr;
    __shared__ float s_nj;
    if (tid < 32) {
        float bv = g_Gamma[tid]; int bi = tid;
#pragma unroll
        for (int t = 1; t < 4; ++t) {
            float v = g_Gamma[tid + 32 * t];
            if (v > bv) { bv = v; bi = tid + 32 * t; }   // increasing idx: strict >
        }
#pragma unroll
        for (int off = 16; off; off >>= 1) {
            float ov = __shfl_down_sync(0xffffffffu, bv, off);
            int   oi = __shfl_down_sync(0xffffffffu, bi, off);
            if (ov > bv || (ov == bv && oi < bi)) { bv = ov; bi = oi; }
        }
        if (tid == 0) {
            s_j = bi;
            s_incr = (bv > 0.9f) ? 1 : 0;
            s_nj = g_n[bi];
        }
    }
    __syncthreads();
    if (s_incr) {
        const int j = s_j;
        if (tid < 64) s_ej[tid] = z[tid] - g_mu[j * ND + tid];
        __syncthreads();
        if (tid < 64) g_mu[j * ND + tid] += s_ej[tid] / (1.0f + s_nj);
        for (int idx = tid; idx < ND * ND; idx += 256)
            g_Smod[idx] = S_in[j * ND * ND + idx] + s_ej[idx >> 6] * s_ej[idx & 63];
        if (tid == 0) { g_n[j] = s_nj + 1.0f; g_modidx = j; }
    } else {
        const int ca = cact[0];
        if (tid < 64) g_mu[ca * ND + tid] = z[tid];
        for (int idx = tid; idx < ND * ND; idx += 256)
            g_Smod[idx] = ((idx >> 6) == (idx & 63)) ? 1.0f : 0.0f;
        if (tid == 0) { g_n[ca] = 1.0f; g_Gamma[ca] = 1.0f; g_active[ca] = 1; g_modidx = ca; }
    }
    __syncthreads();
    if (tid < NC)
        g_sel[tid] = (g_Gamma[tid] > 0.225f && g_active[tid]) ? 1 : 0;
}

// ---------------------------------------------------------------------------
// K3fix (1 block): rebuild ZZ and Vii32 for the single mutated cluster.
// ---------------------------------------------------------------------------
__global__ void __launch_bounds__(128, 6)
k3_fix() {
    const int c = g_modidx;
    const int tid = threadIdx.x;
    __shared__ float s_piv[128];
    __shared__ float s_pk[64];
    const float nc   = g_n[c];
    const float coef = (nc - 1.0f) / nc;
    const float invn = 1.0f / nc;
    const float* mc = &g_mu[c * ND];
    const float4* Sc4 = reinterpret_cast<const float4*>(g_Smod);
    const float4* mc4 = reinterpret_cast<const float4*>(mc);
    float4* Z4 = reinterpret_cast<float4*>(&g_ZZ[c * ND * ND]);
    for (int t = tid; t < ND * ND / 4; t += 128) {
        float4 s = Sc4[t];
        float4 m = mc4[t & 15];
        float mr = mc[t >> 4];
        Z4[t] = make_float4(coef * s.x + mr * m.x, coef * s.y + mr * m.y,
                            coef * s.z + mr * m.z, coef * s.w + mr * m.w);
    }
    const int row = tid >> 1;
    const int c0  = (tid & 1) << 5;
    float a[32];
    const float4* Sr = reinterpret_cast<const float4*>(g_Smod + row * ND + c0);
#pragma unroll
    for (int q = 0; q < 8; ++q) {
        float4 v = Sr[q];
        a[4*q]   = v.x * invn;
        a[4*q+1] = v.y * invn;
        a[4*q+2] = v.z * invn;
        a[4*q+3] = v.w * invn;
    }
    __syncthreads();
    block_elim64f(a, s_piv, s_pk);
    double det = pivot_product(s_pk);
    if (tid == 0) g_Vii32[c] = (float)det;
}

// ---------------------------------------------------------------------------
// K4 (SCREEN, LDL^T): triangular grid — exactly NPAIRS blocks, (i,j) decoded
// from the triangular index. 64 threads/block; warp 0 = cols 0-31, warp 1 =
// cols 32-63 (warp-uniform chunk predicates); rows (r2, r2+32). Pivot COLUMN
// broadcast via double-buffered s_col; f_r = col[r]*(1/d). Outer-product
// update on the lower triangle.  det = prod d_k.
// ---------------------------------------------------------------------------
__global__ void __launch_bounds__(64, 10)
k4_pairs() {
    const int b = blockIdx.x;          // 0 .. NPAIRS-1
    int i = (int)((float)NC - 0.5f
                  - sqrtf(((float)NC - 0.5f) * ((float)NC - 0.5f) - 2.0f * (float)b));
    if (i < 0) i = 0;
    if (i > NC - 2) i = NC - 2;
    while (i > 0 && (i * (2 * NC - i - 1)) / 2 > b) --i;
    while (((i + 1) * (2 * NC - i - 2)) / 2 <= b) ++i;
    const int j = b - (i * (2 * NC - i - 1)) / 2 + i + 1;
    const int tid = threadIdx.x;   // 64
    if (!g_sel[i] || !g_sel[j]) return;     // g_kappa pre-initialized to inf
    __shared__ __align__(16) float s_col[2][64];
    __shared__ float s_pk[64];
    __shared__ float s_muij[64];
    const float ni = g_n[i], nj = g_n[j];
    const float nij = ni + nj;
    s_muij[tid] = (ni * g_mu[i * ND + tid] + nj * g_mu[j * ND + tid]) / nij;
    __syncthreads();
    const float invs = 1.0f / (nij - 1.0f);
    const int r2 = tid & 31;
    const int h  = tid >> 5;          // warp-uniform
    const int c0 = h << 5;
    const int rA = r2, rB = r2 + 32;
    float aA[32], aB[32];
    {
        const float mrB = s_muij[rB];
        const float4* zi4 = reinterpret_cast<const float4*>(&g_ZZ[i * ND * ND + rB * ND + c0]);
        const float4* zj4 = reinterpret_cast<const float4*>(&g_ZZ[j * ND * ND + rB * ND + c0]);
#pragma unroll
        for (int q = 0; q < 8; ++q) {
            float4 x = zi4[q], y = zj4[q];
            aB[4*q]   = (x.x + y.x - mrB * s_muij[c0 + 4*q])     * invs;
            aB[4*q+1] = (x.y + y.y - mrB * s_muij[c0 + 4*q + 1]) * invs;
            aB[4*q+2] = (x.z + y.z - mrB * s_muij[c0 + 4*q + 2]) * invs;
            aB[4*q+3] = (x.w + y.w - mrB * s_muij[c0 + 4*q + 3]) * invs;
        }
    }
    if (h == 0) {
        const float mrA = s_muij[rA];
        const float4* zi4 = reinterpret_cast<const float4*>(&g_ZZ[i * ND * ND + rA * ND]);
        const float4* zj4 = reinterpret_cast<const float4*>(&g_ZZ[j * ND * ND + rA * ND]);
#pragma unroll
        for (int q = 0; q < 8; ++q) {
            float4 x = zi4[q], y = zj4[q];
            aA[4*q]   = (x.x + y.x - mrA * s_muij[4*q])     * invs;
            aA[4*q+1] = (x.y + y.y - mrA * s_muij[4*q + 1]) * invs;
            aA[4*q+2] = (x.z + y.z - mrA * s_muij[4*q + 2]) * invs;
            aA[4*q+3] = (x.w + y.w - mrA * s_muij[4*q + 3]) * invs;
        }
        s_col[0][rA] = aA[0];
        s_col[0][rB] = aB[0];
    }
    __syncthreads();
#pragma unroll
    for (int k = 0; k < 64; ++k) {
        const float* cur = s_col[k & 1];
        const float d = cur[k];
        if (tid == 0) s_pk[k] = d;
        const float invd = __fdividef(1.0f, d);
        const float fA = cur[rA] * invd;
        const float fB = cur[rB] * invd;
        const bool uA = (h == 0) && (rA > k);
        const bool uB = (rB > k);
#pragma unroll
        for (int q = 0; q < 8; ++q) {
            if (c0 + 4*q + 3 > k) {        // warp-uniform live-chunk test
                float4 v = *reinterpret_cast<const float4*>(&cur[c0 + 4*q]);
                if (uA) {
                    aA[4*q]   -= fA * v.x;
                    aA[4*q+1] -= fA * v.y;
                    aA[4*q+2] -= fA * v.z;
                    aA[4*q+3] -= fA * v.w;
                }
                if (uB) {
                    aB[4*q]   -= fB * v.x;
                    aB[4*q+1] -= fB * v.y;
                    aB[4*q+2] -= fB * v.z;
                    aB[4*q+3] -= fB * v.w;
                }
            }
        }
        if (k < 63) {
            const int kk = k + 1;
            if ((kk >> 5) == h) {          // warp-uniform
                float* nxt = s_col[kk & 1];
                const int idx = kk & 31;   // static per unrolled k
                if (h == 0 && rA >= kk) nxt[rA] = aA[idx];
                if (rB >= kk)           nxt[rB] = aB[idx];
            }
        }
        __syncthreads();
    }
    double det = pivot_product(s_pk);
    if (tid == 0) {
        float kap = vij_valid(det) ? ((float)(det / (double)(g_Vii32[i] + g_Vii32[j])))
                                   : f_inf();
        g_kappa[i * NC + j] = kap;
        if (kap < f_inf()) atomicMin(&g_kmin_key, f2key(kap));
    }
}

// ---------------------------------------------------------------------------
// K5a: parallel candidate collection near the global fp32 kmin.
// ---------------------------------------------------------------------------
__global__ void k5a_select() {
    const float kmin = key2f(g_kmin_key);
    if (!(kmin < 3.0e38f)) return;
    const float thr = kmin + (fabsf(kmin) * 1e-3f + 1e-30f);
    const int b = blockIdx.x * 256 + threadIdx.x;
    if (g_kappa[b] <= thr) {
        int p = atomicAdd(&g_ncand, 1);
        if (p < 128) g_cand[p] = b;
    }
}

// ---------------------------------------------------------------------------
// K5b: fp64 recompute of kappa for each candidate pair (same validity mask).
// Denominator uses fp32 Vii (widened) — candidate gaps are orders of
// magnitude, so the ~1e-5 denominator error cannot flip the argmin.
// ---------------------------------------------------------------------------
__global__ void k5b_refine() {
    const int b = blockIdx.x;
    const int ncand = min(g_ncand, 128);
    if (b >= ncand) return;
    const int tid = threadIdx.x;
    __shared__ double s_piv[128];
    __shared__ double s_inv[2];
    __shared__ double s_muij[64];
    const int flat = g_cand[b];
    const int i = flat >> 7;
    const int j = flat & (NC - 1);
    const double ni = (double)g_n[i], nj = (double)g_n[j];
    const double nij = ni + nj;
    if (tid < 64)
        s_muij[tid] = (ni * (double)g_mu[i * ND + tid] + nj * (double)g_mu[j * ND + tid]) / nij;
    __syncthreads();
    const double invs = 1.0 / (nij - 1.0);
    const int row = tid >> 1;
    const int c0  = (tid & 1) << 5;
    const double mr = s_muij[row];
    const float* zi = &g_ZZ[i * ND * ND + row * ND + c0];
    const float* zj = &g_ZZ[j * ND * ND + row * ND + c0];
    double a[32];
#pragma unroll
    for (int q = 0; q < 32; ++q)
        a[q] = ((double)zi[q] + (double)zj[q] - mr * s_muij[c0 + q]) * invs;
    double det = block_det64d(a, s_piv, s_inv);
    if (tid == 0)
        g_kval[b] = vij_valid(det)
                        ? (det / ((double)g_Vii32[i] + (double)g_Vii32[j]))
                        : d_inf();
}

// ---------------------------------------------------------------------------
// K5c: argmin over refined candidates (first-flat-index ties), conditional
// merge, write out = mu * active.
// ---------------------------------------------------------------------------
__global__ void k5c_final(float* __restrict__ out) {
    const int tid = threadIdx.x;   // 256
    __shared__ double s_val[256];
    __shared__ int    s_idx[256];
    const int ncand = min(g_ncand, 128);
    double bv = d_inf(); int bi = 0x7fffffff;
    for (int b = tid; b < ncand; b += 256) {
        double v = g_kval[b]; int fi = g_cand[b];
        if (v < bv || (v == bv && fi < bi)) { bv = v; bi = fi; }
    }
    s_val[tid] = bv; s_idx[tid] = bi;
    __syncthreads();
    for (int s = 128; s; s >>= 1) {
        if (tid < s) {
            double v2 = s_val[tid + s]; int i2 = s_idx[tid + s];
            if (v2 < s_val[tid] || (v2 == s_val[tid] && i2 < s_idx[tid])) {
                s_val[tid] = v2; s_idx[tid] = i2;
            }
        }
        __syncthreads();
    }
    __shared__ int s_mi, s_mj, s_do;
    __shared__ float s_nmi, s_nmj;
    if (tid == 0) {
        s_do = (s_val[0] < 0.9) ? 1 : 0;
        s_mi = s_idx[0] >> 7;
        s_mj = s_idx[0] & (NC - 1);
        if (s_do) { s_nmi = g_n[s_mi]; s_nmj = g_n[s_mj]; }
    }
    __syncthreads();
    if (s_do) {
        if (tid < 64) {
            const int mi = s_mi, mj = s_mj;
            g_mu[mi * ND + tid] =
                (s_nmi * g_mu[mi * ND + tid] + s_nmj * g_mu[mj * ND + tid]) / (s_nmi + s_nmj);
        }
        if (tid == 0) g_active[s_mj] = 0;
    }
    __syncthreads();
    for (int idx = tid; idx < NC * ND; idx += 256)
        out[idx] = g_active[idx >> 6] ? g_mu[idx] : 0.0f;
}

// ---------------------------------------------------------------------------
extern "C" void kernel_launch(void* const* d_in, const int* in_sizes, int n_in,
                              void* d_out, int out_size) {
    const float* z  = (const float*)d_in[0];
    const float* mu = (const float*)d_in[1];
    const float* S  = (const float*)d_in[2];
    const float* n  = (const float*)d_in[3];
    const int*   ca = (const int*)d_in[4];
    float* out = (float*)d_out;

    k1_gamma<<<NC, 64>>>(z, mu, S, n, ca);
    k2_update<<<1, 256>>>(z, S, ca);
    k3_fix<<<1, 128>>>();
    k4_pairs<<<NPAIRS, 64>>>();           // 4th launch -> ncu capture slot
    k5a_select<<<64, 256>>>();
    k5b_refine<<<128, 128>>>();
    k5c_final<<<1, 256>>>(out);
}

// round 13
// speedup vs baseline: 1.9406x; 1.0752x over previous
#include <cuda_runtime.h>
#include <math.h>

#define NC 128   // clusters
#define ND 64    // dimension
#define NPAIRS (NC * (NC - 1) / 2)   // 8128 upper-triangle pairs

// V_FACTOR = 2*pi^32/(64*31!) — reference multiplies det by this in fp32; the
// product underflows (FTZ -> 0) for tiny dets, which drives the validity mask.
#define V_FACTOR_D 3.080513e-20
#define FLT_MIN_NORMAL 1.1754943508222875e-38

// ---------------- device scratch (no allocations allowed) ----------------
static __device__ __align__(16) float g_mu[NC * ND];
static __device__ __align__(16) float g_Smod[ND * ND];   // the one mutated S row
static __device__ __align__(16) float g_ZZ[NC * ND * ND];
static __device__ float  g_n[NC];
static __device__ float  g_Gamma[NC];
static __device__ float  g_Vii32[NC];
static __device__ float  g_kappa[NC * NC];
static __device__ int    g_active[NC];
static __device__ int    g_sel[NC];
static __device__ int    g_modidx;
static __device__ int    g_ncand;
static __device__ int    g_kmin_key;     // order-preserving int key of min kappa
static __device__ int    g_cand[128];
static __device__ double g_kval[128];

__device__ __forceinline__ float  f_inf() { return __int_as_float(0x7f800000); }
__device__ __forceinline__ double d_inf() { return __longlong_as_double(0x7ff0000000000000LL); }

__device__ __forceinline__ int f2key(float f) {
    int b = __float_as_int(f);
    return (b >= 0) ? b : (int)(~(unsigned)b);
}
__device__ __forceinline__ float key2f(int k) {
    return __int_as_float((k >= 0) ? k : (int)(~(unsigned)k));
}

// Emulate the reference's fp32 `V_ij = V_FACTOR*det > 0` test under FTZ.
__device__ __forceinline__ bool vij_valid(double det) {
    return (det > 0.0) && (det * V_FACTOR_D >= FLT_MIN_NORMAL);
}

// ---------------------------------------------------------------------------
// fp32 64x64 forward elimination (128-thread row engine) — used by k3_fix.
// ---------------------------------------------------------------------------
__device__ __forceinline__ void block_elim64f(float a[32], float* s_piv, float* s_pk) {
    const int tid  = threadIdx.x;
    const int row  = tid >> 1;
    const int half = tid & 1;
    const int c0   = half << 5;
    if (row == 0) {
#pragma unroll
        for (int q = 0; q < 8; ++q)
            reinterpret_cast<float4*>(s_piv)[half * 8 + q] =
                make_float4(a[4*q], a[4*q+1], a[4*q+2], a[4*q+3]);
    }
    __syncthreads();
#pragma unroll
    for (int k = 0; k < 64; ++k) {
        const float* buf = s_piv + ((k & 1) << 6);
        float pk = buf[k];
        if (tid == 0) s_pk[k] = pk;
        float cand  = a[k & 31];
        float other = __shfl_xor_sync(0xffffffffu, cand, 1);
        float fr    = ((k >> 5) == half) ? cand : other;
        float f     = __fdividef(fr, pk);
        if (row > k) {
#pragma unroll
            for (int q = 0; q < 8; ++q) {
                if (c0 + 4*q + 3 >= k) {
                    float4 p = reinterpret_cast<const float4*>(buf)[half * 8 + q];
                    a[4*q]   -= f * p.x;
                    a[4*q+1] -= f * p.y;
                    a[4*q+2] -= f * p.z;
                    a[4*q+3] -= f * p.w;
                }
            }
        }
        if (row == k + 1) {
            float* nb = s_piv + (((k + 1) & 1) << 6);
#pragma unroll
            for (int q = 0; q < 8; ++q)
                reinterpret_cast<float4*>(nb)[half * 8 + q] =
                    make_float4(a[4*q], a[4*q+1], a[4*q+2], a[4*q+3]);
        }
        __syncthreads();
    }
}

// Warp-0 product of the 64 stashed pivots (result on thread 0).
__device__ __forceinline__ double pivot_product(const float* s_pk) {
    const int tid = threadIdx.x;
    double v = 1.0;
    if (tid < 32) {
        v = (double)s_pk[tid] * (double)s_pk[tid + 32];
#pragma unroll
        for (int off = 16; off; off >>= 1)
            v *= __shfl_down_sync(0xffffffffu, v, off);
    }
    return v;
}

// ---------------------------------------------------------------------------
// fp64 single-step engine — only candidate refinement (few blocks).
// ---------------------------------------------------------------------------
__device__ __forceinline__ double block_det64d(double a[32], double* s_piv, double* s_inv) {
    const int tid  = threadIdx.x;
    const int row  = tid >> 1;
    const int half = tid & 1;
    const int c0   = half << 5;
    if (row == 0) {
#pragma unroll
        for (int q = 0; q < 16; ++q)
            reinterpret_cast<double2*>(s_piv)[half * 16 + q] = make_double2(a[2*q], a[2*q+1]);
        if (tid == 0) s_inv[0] = 1.0 / a[0];
    }
    __syncthreads();
    double det = 1.0;
#pragma unroll
    for (int k = 0; k < 64; ++k) {
        const double* buf = s_piv + ((k & 1) << 6);
        double pk  = buf[k];
        double ipk = s_inv[k & 1];
        if (tid == 0) det *= pk;
        double cand  = a[k & 31];
        double other = __shfl_xor_sync(0xffffffffu, cand, 1);
        double fr    = ((k >> 5) == half) ? cand : other;
        double f     = fr * ipk;
        if (row > k) {
#pragma unroll
            for (int q = 0; q < 16; ++q) {
                if (c0 + 2*q + 1 >= k) {
                    double2 p = reinterpret_cast<const double2*>(buf)[half * 16 + q];
                    a[2*q]   -= f * p.x;
                    a[2*q+1] -= f * p.y;
                }
            }
        }
        if (row == k + 1) {
            double* nb = s_piv + (((k + 1) & 1) << 6);
#pragma unroll
            for (int q = 0; q < 16; ++q)
                reinterpret_cast<double2*>(nb)[half * 16 + q] = make_double2(a[2*q], a[2*q+1]);
            if (((k + 1) >> 5) == half) s_inv[(k + 1) & 1] = 1.0 / a[(k + 1) & 31];
        }
        __syncthreads();
    }
    return det;
}

// ---------------------------------------------------------------------------
// K1 (column-LDL^T engine, 64 threads): per cluster c —
//  - copy mu / n / active into working state; init g_kappa row to +inf
//  - ZZ_c = ((n-1)/n) S + mu mu^T
//  - LDL^T of S/n with folded RHS solve (x in warp-0 registers):
//    Vii32 = prod d_k; d2_mah = sum x_k^2/d_k; d2_euc from e pre-loop.
//  - Gamma = active ? exp(-d2) : 0
// ---------------------------------------------------------------------------
__global__ void __launch_bounds__(64, 10)
k1_gamma(const float* __restrict__ z, const float* __restrict__ mu_in,
         const float* __restrict__ S_in, const float* __restrict__ n_in,
         const int* __restrict__ cact) {
    const int c = blockIdx.x;
    const int tid = threadIdx.x;   // 64
    __shared__ __align__(16) float s_col[2][64];
    __shared__ float s_pk[64];
    __shared__ float s_xk[64];
    const float nc = n_in[c];
    const int lane = tid & 31;
    const int h    = tid >> 5;      // warp-uniform
    const int c0   = h << 5;
    const int rA = lane, rB = lane + 32;
    // state copy + kappa row init
    {
        float m = mu_in[c * ND + tid];
        g_mu[c * ND + tid] = m;
    }
    g_kappa[c * NC + tid]      = f_inf();
    g_kappa[c * NC + tid + 64] = f_inf();
    if (tid == 0) {
        g_n[c] = nc;
        g_active[c] = (c < cact[0]) ? 1 : 0;
        if (c == 0) { g_kmin_key = 0x7f800000; g_ncand = 0; }
    }
    // ZZ build from INPUT S, mu
    {
        const float coef = (nc - 1.0f) / nc;
        const float* mc = mu_in + c * ND;
        const float4* Sc4 = reinterpret_cast<const float4*>(S_in + c * ND * ND);
        const float4* mc4 = reinterpret_cast<const float4*>(mc);
        float4* Z4 = reinterpret_cast<float4*>(&g_ZZ[c * ND * ND]);
        for (int t = tid; t < ND * ND / 4; t += 64) {
            float4 s = Sc4[t];
            float4 m = mc4[t & 15];
            float mr = mc[t >> 4];
            Z4[t] = make_float4(coef * s.x + mr * m.x, coef * s.y + mr * m.y,
                                coef * s.z + mr * m.z, coef * s.w + mr * m.w);
        }
    }
    // matrix rows (S/n) for this thread
    const float invn = 1.0f / nc;
    float aA[32], aB[32];
    {
        const float4* SB = reinterpret_cast<const float4*>(S_in + c * ND * ND + rB * ND + c0);
#pragma unroll
        for (int q = 0; q < 8; ++q) {
            float4 v = SB[q];
            aB[4*q]   = v.x * invn;
            aB[4*q+1] = v.y * invn;
            aB[4*q+2] = v.z * invn;
            aB[4*q+3] = v.w * invn;
        }
    }
    float xA = 0.0f, xB = 0.0f;
    float deuc = 0.0f;   // valid on warp-0 lane 0 after reduction
    if (h == 0) {
        const float4* SA = reinterpret_cast<const float4*>(S_in + c * ND * ND + rA * ND);
#pragma unroll
        for (int q = 0; q < 8; ++q) {
            float4 v = SA[q];
            aA[4*q]   = v.x * invn;
            aA[4*q+1] = v.y * invn;
            aA[4*q+2] = v.z * invn;
            aA[4*q+3] = v.w * invn;
        }
        xA = z[rA] - mu_in[c * ND + rA];
        xB = z[rB] - mu_in[c * ND + rB];
        deuc = xA * xA + xB * xB;
#pragma unroll
        for (int off = 16; off; off >>= 1)
            deuc += __shfl_down_sync(0xffffffffu, deuc, off);
        // initial publish: column 0 + x[0]
        s_col[0][rA] = aA[0];
        s_col[0][rB] = aB[0];
        if (rA == 0) s_xk[0] = xA;
    }
    __syncthreads();
#pragma unroll
    for (int k = 0; k < 64; ++k) {
        const float* cur = s_col[k & 1];
        const float d = cur[k];
        if (tid == 0) s_pk[k] = d;
        const float invd = __fdividef(1.0f, d);
        const float fA = cur[rA] * invd;
        const float fB = cur[rB] * invd;
        const float xk = s_xk[k];
        const bool uA = (h == 0) && (rA > k);
        const bool uB = (rB > k);
#pragma unroll
        for (int q = 0; q < 8; ++q) {
            if (c0 + 4*q + 3 > k) {        // warp-uniform live-chunk test
                float4 v = *reinterpret_cast<const float4*>(&cur[c0 + 4*q]);
                if (uA) {
                    aA[4*q]   -= fA * v.x;
                    aA[4*q+1] -= fA * v.y;
                    aA[4*q+2] -= fA * v.z;
                    aA[4*q+3] -= fA * v.w;
                }
                if (uB) {
                    aB[4*q]   -= fB * v.x;
                    aB[4*q+1] -= fB * v.y;
                    aB[4*q+2] -= fB * v.z;
                    aB[4*q+3] -= fB * v.w;
                }
            }
        }
        if (h == 0) {
            if (rA > k) xA -= fA * xk;
            if (rB > k) xB -= fB * xk;
        }
        if (k < 63) {
            const int kk = k + 1;
            if ((kk >> 5) == h) {          // warp-uniform column publish
                float* nxt = s_col[kk & 1];
                const int idx = kk & 31;
                if (h == 0 && rA >= kk) nxt[rA] = aA[idx];
                if (rB >= kk)           nxt[rB] = aB[idx];
            }
            if (h == 0 && rA == (kk & 31))   // x publish (warp 0 owns x)
                s_xk[kk] = (kk < 32) ? xA : xB;
        }
        __syncthreads();
    }
    // post-loop reductions (warp 0): d2_mah, det
    if (tid < 32) {
        float x0 = s_xk[tid], x1 = s_xk[tid + 32];
        float p0 = s_pk[tid], p1 = s_pk[tid + 32];
        double dmah = (double)(x0 * x0) / (double)p0 + (double)(x1 * x1) / (double)p1;
        double dprod = (double)p0 * (double)p1;
#pragma unroll
        for (int off = 16; off; off >>= 1) {
            dmah  += __shfl_down_sync(0xffffffffu, dmah, off);
            dprod *= __shfl_down_sync(0xffffffffu, dprod, off);
        }
        if (tid == 0) {
            float d2 = (nc < 100.0f) ? deuc : (float)dmah;
            g_Gamma[c] = (c < cact[0]) ? expf(-d2) : 0.0f;
            g_Vii32[c] = (float)dprod;
        }
    }
}

// ---------------------------------------------------------------------------
// K2: warp-parallel argmax Gamma (first-index ties), incremental update or
// spawn (S mutation stored as g_Smod + g_modidx), then sel.
// ---------------------------------------------------------------------------
__global__ void k2_update(const float* __restrict__ z, const float* __restrict__ S_in,
                          const int* __restrict__ cact) {
    const int tid = threadIdx.x;   // 256
    __shared__ float s_ej[64];
    __shared__ int s_j, s_incr;
    __shared__ float s_nj;
    if (tid < 32) {
        float bv = g_Gamma[tid]; int bi = tid;
#pragma unroll
        for (int t = 1; t < 4; ++t) {
            float v = g_Gamma[tid + 32 * t];
            if (v > bv) { bv = v; bi = tid + 32 * t; }   // increasing idx: strict >
        }
#pragma unroll
        for (int off = 16; off; off >>= 1) {
            float ov = __shfl_down_sync(0xffffffffu, bv, off);
            int   oi = __shfl_down_sync(0xffffffffu, bi, off);
            if (ov > bv || (ov == bv && oi < bi)) { bv = ov; bi = oi; }
        }
        if (tid == 0) {
            s_j = bi;
            s_incr = (bv > 0.9f) ? 1 : 0;
            s_nj = g_n[bi];
        }
    }
    __syncthreads();
    if (s_incr) {
        const int j = s_j;
        if (tid < 64) s_ej[tid] = z[tid] - g_mu[j * ND + tid];
        __syncthreads();
        if (tid < 64) g_mu[j * ND + tid] += s_ej[tid] / (1.0f + s_nj);
        for (int idx = tid; idx < ND * ND; idx += 256)
            g_Smod[idx] = S_in[j * ND * ND + idx] + s_ej[idx >> 6] * s_ej[idx & 63];
        if (tid == 0) { g_n[j] = s_nj + 1.0f; g_modidx = j; }
    } else {
        const int ca = cact[0];
        if (tid < 64) g_mu[ca * ND + tid] = z[tid];
        for (int idx = tid; idx < ND * ND; idx += 256)
            g_Smod[idx] = ((idx >> 6) == (idx & 63)) ? 1.0f : 0.0f;
        if (tid == 0) { g_n[ca] = 1.0f; g_Gamma[ca] = 1.0f; g_active[ca] = 1; g_modidx = ca; }
    }
    __syncthreads();
    if (tid < NC)
        g_sel[tid] = (g_Gamma[tid] > 0.225f && g_active[tid]) ? 1 : 0;
}

// ---------------------------------------------------------------------------
// K3fix (1 block): rebuild ZZ and Vii32 for the single mutated cluster.
// ---------------------------------------------------------------------------
__global__ void __launch_bounds__(128, 6)
k3_fix() {
    const int c = g_modidx;
    const int tid = threadIdx.x;
    __shared__ float s_piv[128];
    __shared__ float s_pk[64];
    const float nc   = g_n[c];
    const float coef = (nc - 1.0f) / nc;
    const float invn = 1.0f / nc;
    const float* mc = &g_mu[c * ND];
    const float4* Sc4 = reinterpret_cast<const float4*>(g_Smod);
    const float4* mc4 = reinterpret_cast<const float4*>(mc);
    float4* Z4 = reinterpret_cast<float4*>(&g_ZZ[c * ND * ND]);
    for (int t = tid; t < ND * ND / 4; t += 128) {
        float4 s = Sc4[t];
        float4 m = mc4[t & 15];
        float mr = mc[t >> 4];
        Z4[t] = make_float4(coef * s.x + mr * m.x, coef * s.y + mr * m.y,
                            coef * s.z + mr * m.z, coef * s.w + mr * m.w);
    }
    const int row = tid >> 1;
    const int c0  = (tid & 1) << 5;
    float a[32];
    const float4* Sr = reinterpret_cast<const float4*>(g_Smod + row * ND + c0);
#pragma unroll
    for (int q = 0; q < 8; ++q) {
        float4 v = Sr[q];
        a[4*q]   = v.x * invn;
        a[4*q+1] = v.y * invn;
        a[4*q+2] = v.z * invn;
        a[4*q+3] = v.w * invn;
    }
    __syncthreads();
    block_elim64f(a, s_piv, s_pk);
    double det = pivot_product(s_pk);
    if (tid == 0) g_Vii32[c] = (float)det;
}

// ---------------------------------------------------------------------------
// K4 (SCREEN, LDL^T): triangular grid, 64 threads/block; warp 0 = cols 0-31,
// warp 1 = cols 32-63 (warp-uniform predicates); rows (r2, r2+32).
// Critical-path surgery vs round 12:
//  * reciprocal HOISTED: the publisher of column kk also publishes
//    s_invd[kk] = 1/diag (computed in the shadow of the chunk loop).
//  * EARLY publish: column kk is published (val = a[idx] - f*cur[kk], the
//    exact chunk-loop FMA for that element) BEFORE the bulk chunk updates.
//  * warp-0 retirement: steps 32..63 run warp-1-solo with __syncwarp (warp 0
//    is provably idle there: all its column chunks are dead).
// Arithmetic is bit-identical to round 12's engine.
// ---------------------------------------------------------------------------
__global__ void __launch_bounds__(64, 10)
k4_pairs() {
    const int b = blockIdx.x;          // 0 .. NPAIRS-1
    int i = (int)((float)NC - 0.5f
                  - sqrtf(((float)NC - 0.5f) * ((float)NC - 0.5f) - 2.0f * (float)b));
    if (i < 0) i = 0;
    if (i > NC - 2) i = NC - 2;
    while (i > 0 && (i * (2 * NC - i - 1)) / 2 > b) --i;
    while (((i + 1) * (2 * NC - i - 2)) / 2 <= b) ++i;
    const int j = b - (i * (2 * NC - i - 1)) / 2 + i + 1;
    const int tid = threadIdx.x;   // 64
    if (!g_sel[i] || !g_sel[j]) return;     // g_kappa pre-initialized to inf
    __shared__ __align__(16) float s_col[2][64];
    __shared__ float s_pk[64];
    __shared__ float s_invd[64];
    __shared__ float s_muij[64];
    const float ni = g_n[i], nj = g_n[j];
    const float nij = ni + nj;
    s_muij[tid] = (ni * g_mu[i * ND + tid] + nj * g_mu[j * ND + tid]) / nij;
    __syncthreads();
    const float invs = 1.0f / (nij - 1.0f);
    const int r2 = tid & 31;
    const int h  = tid >> 5;          // warp-uniform
    const int c0 = h << 5;
    const int rA = r2, rB = r2 + 32;
    float aA[32], aB[32];
    {
        const float mrB = s_muij[rB];
        const float4* zi4 = reinterpret_cast<const float4*>(&g_ZZ[i * ND * ND + rB * ND + c0]);
        const float4* zj4 = reinterpret_cast<const float4*>(&g_ZZ[j * ND * ND + rB * ND + c0]);
#pragma unroll
        for (int q = 0; q < 8; ++q) {
            float4 x = zi4[q], y = zj4[q];
            aB[4*q]   = (x.x + y.x - mrB * s_muij[c0 + 4*q])     * invs;
            aB[4*q+1] = (x.y + y.y - mrB * s_muij[c0 + 4*q + 1]) * invs;
            aB[4*q+2] = (x.z + y.z - mrB * s_muij[c0 + 4*q + 2]) * invs;
            aB[4*q+3] = (x.w + y.w - mrB * s_muij[c0 + 4*q + 3]) * invs;
        }
    }
    if (h == 0) {
        const float mrA = s_muij[rA];
        const float4* zi4 = reinterpret_cast<const float4*>(&g_ZZ[i * ND * ND + rA * ND]);
        const float4* zj4 = reinterpret_cast<const float4*>(&g_ZZ[j * ND * ND + rA * ND]);
#pragma unroll
        for (int q = 0; q < 8; ++q) {
            float4 x = zi4[q], y = zj4[q];
            aA[4*q]   = (x.x + y.x - mrA * s_muij[4*q])     * invs;
            aA[4*q+1] = (x.y + y.y - mrA * s_muij[4*q + 1]) * invs;
            aA[4*q+2] = (x.z + y.z - mrA * s_muij[4*q + 2]) * invs;
            aA[4*q+3] = (x.w + y.w - mrA * s_muij[4*q + 3]) * invs;
        }
        s_col[0][rA] = aA[0];
        s_col[0][rB] = aB[0];
        if (rA == 0) s_invd[0] = __fdividef(1.0f, aA[0]);
    }
    __syncthreads();
    // ---- phase 1: k = 0..31, full block ----
#pragma unroll
    for (int k = 0; k < 32; ++k) {
        const float* cur = s_col[k & 1];
        const float invd = s_invd[k];
        if (tid == 0) s_pk[k] = cur[k];
        const float fA = cur[rA] * invd;
        const float fB = cur[rB] * invd;
        // early publish of column k+1 (+ its reciprocal)
        {
            const int kk = k + 1;
            if ((kk >> 5) == h) {          // h=0 for kk<32; kk==32 -> h=1
                float* nxt = s_col[kk & 1];
                const int idx = kk & 31;
                const float ck = cur[kk];
                if (h == 0) {
                    if (rA >= kk) {
                        float val = aA[idx] - fA * ck;
                        nxt[rA] = val;
                        if (rA == kk) s_invd[kk] = __fdividef(1.0f, val);
                    }
                    {   // rB (= r2+32) always >= 32 > kk here
                        float val = aB[idx] - fB * ck;
                        nxt[rB] = val;
                    }
                } else {                    // kk == 32 only
                    float val = aB[idx] - fB * ck;   // idx = 0
                    nxt[rB] = val;                   // rB >= 32 == kk
                    if (rB == kk) s_invd[kk] = __fdividef(1.0f, val);
                }
            }
        }
        // bulk chunk updates (in the shadow of the publish)
        const bool uA = (h == 0) && (rA > k);
        const bool uB = (rB > k);
#pragma unroll
        for (int q = 0; q < 8; ++q) {
            if (c0 + 4*q + 3 > k) {        // warp-uniform live-chunk test
                float4 v = *reinterpret_cast<const float4*>(&cur[c0 + 4*q]);
                if (uA) {
                    aA[4*q]   -= fA * v.x;
                    aA[4*q+1] -= fA * v.y;
                    aA[4*q+2] -= fA * v.z;
                    aA[4*q+3] -= fA * v.w;
                }
                if (uB) {
                    aB[4*q]   -= fB * v.x;
                    aB[4*q+1] -= fB * v.y;
                    aB[4*q+2] -= fB * v.z;
                    aB[4*q+3] -= fB * v.w;
                }
            }
        }
        __syncthreads();
    }
    // ---- phase 2: k = 32..63, warp 1 only (warp 0 provably idle) ----
    if (h == 1) {
#pragma unroll
        for (int k = 32; k < 64; ++k) {
            const float* cur = s_col[k & 1];
            const float invd = s_invd[k];
            if (tid == 32) s_pk[k] = cur[k];
            const float fB = cur[rB] * invd;
            if (k < 63) {
                const int kk = k + 1;      // always in half 1
                float* nxt = s_col[kk & 1];
                const int idx = kk & 31;
                const float ck = cur[kk];
                if (rB >= kk) {
                    float val = aB[idx] - fB * ck;
                    nxt[rB] = val;
                    if (rB == kk) s_invd[kk] = __fdividef(1.0f, val);
                }
            }
            if (rB > k) {
#pragma unroll
                for (int q = 0; q < 8; ++q) {
                    if (32 + 4*q + 3 > k) {
                        float4 v = *reinterpret_cast<const float4*>(&cur[32 + 4*q]);
                        aB[4*q]   -= fB * v.x;
                        aB[4*q+1] -= fB * v.y;
                        aB[4*q+2] -= fB * v.z;
                        aB[4*q+3] -= fB * v.w;
                    }
                }
            }
            __syncwarp();
        }
    }
    __syncthreads();
    double det = pivot_product(s_pk);
    if (tid == 0) {
        float kap = vij_valid(det) ? ((float)(det / (double)(g_Vii32[i] + g_Vii32[j])))
                                   : f_inf();
        g_kappa[i * NC + j] = kap;
        if (kap < f_inf()) atomicMin(&g_kmin_key, f2key(kap));
    }
}

// ---------------------------------------------------------------------------
// K5a: parallel candidate collection near the global fp32 kmin.
// ---------------------------------------------------------------------------
__global__ void k5a_select() {
    const float kmin = key2f(g_kmin_key);
    if (!(kmin < 3.0e38f)) return;
    const float thr = kmin + (fabsf(kmin) * 1e-3f + 1e-30f);
    const int b = blockIdx.x * 256 + threadIdx.x;
    if (g_kappa[b] <= thr) {
        int p = atomicAdd(&g_ncand, 1);
        if (p < 128) g_cand[p] = b;
    }
}

// ---------------------------------------------------------------------------
// K5b: fp64 recompute of kappa for each candidate pair (same validity mask).
// Denominator uses fp32 Vii (widened) — candidate gaps are orders of
// magnitude, so the ~1e-5 denominator error cannot flip the argmin.
// ---------------------------------------------------------------------------
__global__ void k5b_refine() {
    const int b = blockIdx.x;
    const int ncand = min(g_ncand, 128);
    if (b >= ncand) return;
    const int tid = threadIdx.x;
    __shared__ double s_piv[128];
    __shared__ double s_inv[2];
    __shared__ double s_muij[64];
    const int flat = g_cand[b];
    const int i = flat >> 7;
    const int j = flat & (NC - 1);
    const double ni = (double)g_n[i], nj = (double)g_n[j];
    const double nij = ni + nj;
    if (tid < 64)
        s_muij[tid] = (ni * (double)g_mu[i * ND + tid] + nj * (double)g_mu[j * ND + tid]) / nij;
    __syncthreads();
    const double invs = 1.0 / (nij - 1.0);
    const int row = tid >> 1;
    const int c0  = (tid & 1) << 5;
    const double mr = s_muij[row];
    const float* zi = &g_ZZ[i * ND * ND + row * ND + c0];
    const float* zj = &g_ZZ[j * ND * ND + row * ND + c0];
    double a[32];
#pragma unroll
    for (int q = 0; q < 32; ++q)
        a[q] = ((double)zi[q] + (double)zj[q] - mr * s_muij[c0 + q]) * invs;
    double det = block_det64d(a, s_piv, s_inv);
    if (tid == 0)
        g_kval[b] = vij_valid(det)
                        ? (det / ((double)g_Vii32[i] + (double)g_Vii32[j]))
                        : d_inf();
}

// ---------------------------------------------------------------------------
// K5c: argmin over refined candidates (first-flat-index ties), conditional
// merge, write out = mu * active.
// ---------------------------------------------------------------------------
__global__ void k5c_final(float* __restrict__ out) {
    const int tid = threadIdx.x;   // 256
    __shared__ double s_val[256];
    __shared__ int    s_idx[256];
    const int ncand = min(g_ncand, 128);
    double bv = d_inf(); int bi = 0x7fffffff;
    for (int b = tid; b < ncand; b += 256) {
        double v = g_kval[b]; int fi = g_cand[b];
        if (v < bv || (v == bv && fi < bi)) { bv = v; bi = fi; }
    }
    s_val[tid] = bv; s_idx[tid] = bi;
    __syncthreads();
    for (int s = 128; s; s >>= 1) {
        if (tid < s) {
            double v2 = s_val[tid + s]; int i2 = s_idx[tid + s];
            if (v2 < s_val[tid] || (v2 == s_val[tid] && i2 < s_idx[tid])) {
                s_val[tid] = v2; s_idx[tid] = i2;
            }
        }
        __syncthreads();
    }
    __shared__ int s_mi, s_mj, s_do;
    __shared__ float s_nmi, s_nmj;
    if (tid == 0) {
        s_do = (s_val[0] < 0.9) ? 1 : 0;
        s_mi = s_idx[0] >> 7;
        s_mj = s_idx[0] & (NC - 1);
        if (s_do) { s_nmi = g_n[s_mi]; s_nmj = g_n[s_mj]; }
    }
    __syncthreads();
    if (s_do) {
        if (tid < 64) {
            const int mi = s_mi, mj = s_mj;
            g_mu[mi * ND + tid] =
                (s_nmi * g_mu[mi * ND + tid] + s_nmj * g_mu[mj * ND + tid]) / (s_nmi + s_nmj);
        }
        if (tid == 0) g_active[s_mj] = 0;
    }
    __syncthreads();
    for (int idx = tid; idx < NC * ND; idx += 256)
        out[idx] = g_active[idx >> 6] ? g_mu[idx] : 0.0f;
}

// ---------------------------------------------------------------------------
extern "C" void kernel_launch(void* const* d_in, const int* in_sizes, int n_in,
                              void* d_out, int out_size) {
    const float* z  = (const float*)d_in[0];
    const float* mu = (const float*)d_in[1];
    const float* S  = (const float*)d_in[2];
    const float* n  = (const float*)d_in[3];
    const int*   ca = (const int*)d_in[4];
    float* out = (float*)d_out;

    k1_gamma<<<NC, 64>>>(z, mu, S, n, ca);
    k2_update<<<1, 256>>>(z, S, ca);
    k3_fix<<<1, 128>>>();
    k4_pairs<<<NPAIRS, 64>>>();           // 4th launch -> ncu capture slot
    k5a_select<<<64, 256>>>();
    k5b_refine<<<128, 128>>>();
    k5c_final<<<1, 256>>>(out);
}